// round 1
// baseline (speedup 1.0000x reference)
#include <cuda_runtime.h>
#include <cstddef>

#define BB   8
#define TT   768
#define CC   512
#define FF   2048
#define HH   8
#define KC   64
#define LL   6
#define BT   (BB*TT)      // 6144
#define NWIN 9

// ---------------- scratch (device globals: allocation-free) ----------------
__device__ float g_x [BT*CC];
__device__ float g_q [BT*CC];
__device__ float g_k [BT*CC];
__device__ float g_v [BT*CC];
__device__ float g_ao[BT*CC];
__device__ float g_y [BT*CC];
__device__ float g_h1[BT*FF];
__device__ float g_p [(size_t)BB*HH*TT*TT];   // 151 MB attention probs

// ---------------- elementwise: out[i] = in[i] * mask[row] ------------------
__global__ void maskmul_kernel(const float* __restrict__ in,
                               const float* __restrict__ mask,
                               float* __restrict__ out, int n)
{
    int i = blockIdx.x * blockDim.x + threadIdx.x;
    if (i < n) out[i] = in[i] * mask[i / CC];
}

// ---------------- dense SGEMM: C = rowmask(A)[M,K] @ B[K,N] + bias ---------
// 128x128 tile, BK=8, 256 threads, 8x8 per thread. M%128==0, N%128==0, K%8==0.
__global__ void __launch_bounds__(256)
sgemm_kernel(const float* __restrict__ A, const float* __restrict__ B,
             const float* __restrict__ bias, const float* __restrict__ rowmask,
             float* __restrict__ C, int M, int N, int K, int relu)
{
    __shared__ float As[8][128];
    __shared__ float Bs[8][128];
    int tid = threadIdx.x;
    int tx = tid & 15, ty = tid >> 4;
    int bm = blockIdx.y * 128, bn = blockIdx.x * 128;

    int a_row = tid >> 1;            // 0..127
    int a_col = (tid & 1) * 4;       // 0 or 4
    int b_row = tid >> 5;            // 0..7
    int b_col = (tid & 31) * 4;      // 0..124

    float am = rowmask ? rowmask[bm + a_row] : 1.0f;
    const float* Aptr = A + (size_t)(bm + a_row) * K + a_col;
    const float* Bptr = B + (size_t)b_row * N + bn + b_col;

    float acc[8][8];
    #pragma unroll
    for (int i = 0; i < 8; i++)
        #pragma unroll
        for (int j = 0; j < 8; j++) acc[i][j] = 0.0f;

    for (int kt = 0; kt < K; kt += 8) {
        float4 av = *(const float4*)(Aptr + kt);
        As[a_col+0][a_row] = av.x * am;
        As[a_col+1][a_row] = av.y * am;
        As[a_col+2][a_row] = av.z * am;
        As[a_col+3][a_row] = av.w * am;
        float4 bv = *(const float4*)(Bptr + (size_t)kt * N);
        *(float4*)&Bs[b_row][b_col] = bv;
        __syncthreads();
        #pragma unroll
        for (int k = 0; k < 8; k++) {
            float ar[8], br[8];
            *(float4*)(ar  ) = *(const float4*)&As[k][ty*8];
            *(float4*)(ar+4) = *(const float4*)&As[k][ty*8+4];
            *(float4*)(br  ) = *(const float4*)&Bs[k][tx*8];
            *(float4*)(br+4) = *(const float4*)&Bs[k][tx*8+4];
            #pragma unroll
            for (int i = 0; i < 8; i++)
                #pragma unroll
                for (int j = 0; j < 8; j++)
                    acc[i][j] += ar[i] * br[j];
        }
        __syncthreads();
    }

    #pragma unroll
    for (int i = 0; i < 8; i++) {
        int m = bm + ty*8 + i;
        #pragma unroll
        for (int j = 0; j < 8; j += 4) {
            int n = bn + tx*8 + j;
            float4 o;
            o.x = acc[i][j+0] + (bias ? bias[n+0] : 0.f);
            o.y = acc[i][j+1] + (bias ? bias[n+1] : 0.f);
            o.z = acc[i][j+2] + (bias ? bias[n+2] : 0.f);
            o.w = acc[i][j+3] + (bias ? bias[n+3] : 0.f);
            if (relu) {
                o.x = fmaxf(o.x, 0.f); o.y = fmaxf(o.y, 0.f);
                o.z = fmaxf(o.z, 0.f); o.w = fmaxf(o.w, 0.f);
            }
            *(float4*)(C + (size_t)m * N + n) = o;
        }
    }
}

// ---------------- scores[b,h,i,j] = scale * <Q_i, K_j> ---------------------
// per (b,h): Q[768,64] @ K^T -> [768,768]. 64x64 tile, 256 thr, 4x4/thread.
__global__ void __launch_bounds__(256)
scores_kernel(const float* __restrict__ Q, const float* __restrict__ Km,
              float* __restrict__ P)
{
    __shared__ float Qs[64][65];
    __shared__ float Ks[64][65];
    int tid = threadIdx.x;
    int bh = blockIdx.z;
    int b = bh >> 3, h = bh & 7;
    int ti0 = blockIdx.y * 64, tj0 = blockIdx.x * 64;
    int lr = tid >> 4, lc = (tid & 15) * 4;

    const float* qbase = Q + ((size_t)(b*TT + ti0)) * CC + h*KC;
    const float* kbase = Km + ((size_t)(b*TT + tj0)) * CC + h*KC;
    #pragma unroll
    for (int rr = 0; rr < 64; rr += 16) {
        float4 qv = *(const float4*)(qbase + (size_t)(lr+rr)*CC + lc);
        Qs[lr+rr][lc+0]=qv.x; Qs[lr+rr][lc+1]=qv.y; Qs[lr+rr][lc+2]=qv.z; Qs[lr+rr][lc+3]=qv.w;
        float4 kv = *(const float4*)(kbase + (size_t)(lr+rr)*CC + lc);
        Ks[lr+rr][lc+0]=kv.x; Ks[lr+rr][lc+1]=kv.y; Ks[lr+rr][lc+2]=kv.z; Ks[lr+rr][lc+3]=kv.w;
    }
    __syncthreads();

    int tx = tid & 15, ty = tid >> 4;
    float acc[4][4];
    #pragma unroll
    for (int i=0;i<4;i++) { acc[i][0]=0;acc[i][1]=0;acc[i][2]=0;acc[i][3]=0; }

    #pragma unroll 4
    for (int d = 0; d < 64; d++) {
        float qr[4], kr[4];
        #pragma unroll
        for (int i = 0; i < 4; i++) qr[i] = Qs[ty*4+i][d];
        #pragma unroll
        for (int j = 0; j < 4; j++) kr[j] = Ks[tx*4+j][d];
        #pragma unroll
        for (int i = 0; i < 4; i++)
            #pragma unroll
            for (int j = 0; j < 4; j++)
                acc[i][j] += qr[i] * kr[j];
    }
    const float scale = 0.125f;  // 1/sqrt(64)
    #pragma unroll
    for (int i = 0; i < 4; i++) {
        float4 o = { acc[i][0]*scale, acc[i][1]*scale, acc[i][2]*scale, acc[i][3]*scale };
        *(float4*)(P + ((size_t)bh*TT + ti0 + ty*4 + i) * TT + tj0 + tx*4) = o;
    }
}

// ---------------- fused rel-band + mask + softmax (in-place on P) ----------
__global__ void __launch_bounds__(256)
softmax_kernel(float* __restrict__ P, const float* __restrict__ Q,
               const float* __restrict__ rk, const float* __restrict__ mask)
{
    int row = blockIdx.x;          // = bh*T + qi
    int qi  = row % TT;
    int bh  = row / TT;
    int b = bh >> 3, h = bh & 7;
    int tid = threadIdx.x;

    __shared__ float rel9[NWIN];
    __shared__ float red[256];

    if (tid < NWIN) {
        const float* qv  = Q + ((size_t)(b*TT + qi)) * CC + h*KC;
        const float* rkj = rk + tid * KC;
        float s = 0.f;
        #pragma unroll 8
        for (int d = 0; d < KC; d++) s += qv[d] * rkj[d];
        rel9[tid] = s * 0.125f;
    }
    __syncthreads();

    float mq = mask[b*TT + qi];
    float* prow = P + (size_t)row * TT;
    float vals[3];
    float mx = -1e30f;
    #pragma unroll
    for (int u = 0; u < 3; u++) {
        int k = tid + u*256;
        float s = prow[k];
        int j = k - qi + 4;
        if ((unsigned)j < (unsigned)NWIN) s += rel9[j];
        if (mq * mask[b*TT + k] == 0.f) s = -10000.f;
        vals[u] = s;
        mx = fmaxf(mx, s);
    }
    red[tid] = mx; __syncthreads();
    for (int s = 128; s > 0; s >>= 1) {
        if (tid < s) red[tid] = fmaxf(red[tid], red[tid+s]);
        __syncthreads();
    }
    mx = red[0]; __syncthreads();

    float sum = 0.f;
    #pragma unroll
    for (int u = 0; u < 3; u++) { vals[u] = expf(vals[u] - mx); sum += vals[u]; }
    red[tid] = sum; __syncthreads();
    for (int s = 128; s > 0; s >>= 1) {
        if (tid < s) red[tid] += red[tid+s];
        __syncthreads();
    }
    float inv = 1.f / red[0];
    #pragma unroll
    for (int u = 0; u < 3; u++) prow[tid + u*256] = vals[u] * inv;
}

// ---------------- O = P @ V (+ rel_v band), written as [B,T,C] -------------
__global__ void __launch_bounds__(256)
pv_kernel(const float* __restrict__ P, const float* __restrict__ V,
          const float* __restrict__ rv, float* __restrict__ O)
{
    __shared__ float Ps[64][65];
    __shared__ float Vs[64][65];
    int tid = threadIdx.x;
    int bh = blockIdx.y;
    int b = bh >> 3, h = bh & 7;
    int ti0 = blockIdx.x * 64;
    int lr = tid >> 4, lc = (tid & 15) * 4;
    int tx = tid & 15, ty = tid >> 4;

    float acc[4][4];
    #pragma unroll
    for (int i=0;i<4;i++) { acc[i][0]=0;acc[i][1]=0;acc[i][2]=0;acc[i][3]=0; }

    for (int kk = 0; kk < TT; kk += 64) {
        #pragma unroll
        for (int rr = 0; rr < 64; rr += 16) {
            float4 p4 = *(const float4*)(P + ((size_t)bh*TT + ti0 + lr+rr) * TT + kk + lc);
            Ps[lr+rr][lc+0]=p4.x; Ps[lr+rr][lc+1]=p4.y; Ps[lr+rr][lc+2]=p4.z; Ps[lr+rr][lc+3]=p4.w;
            float4 v4 = *(const float4*)(V + ((size_t)(b*TT + kk + lr+rr)) * CC + h*KC + lc);
            Vs[lr+rr][lc+0]=v4.x; Vs[lr+rr][lc+1]=v4.y; Vs[lr+rr][lc+2]=v4.z; Vs[lr+rr][lc+3]=v4.w;
        }
        __syncthreads();
        #pragma unroll 4
        for (int k = 0; k < 64; k++) {
            float pr[4], vr[4];
            #pragma unroll
            for (int i = 0; i < 4; i++) pr[i] = Ps[ty*4+i][k];
            #pragma unroll
            for (int j = 0; j < 4; j++) vr[j] = Vs[k][tx*4+j];
            #pragma unroll
            for (int i = 0; i < 4; i++)
                #pragma unroll
                for (int j = 0; j < 4; j++)
                    acc[i][j] += pr[i] * vr[j];
        }
        __syncthreads();
    }

    // rel_v band epilogue: out[t,d] += sum_j p[t, t+j-4] * rv[j, d]
    #pragma unroll
    for (int i = 0; i < 4; i++) {
        int t = ti0 + ty*4 + i;
        #pragma unroll
        for (int j5 = 0; j5 < NWIN; j5++) {
            int k = t + j5 - 4;
            if (k >= 0 && k < TT) {
                float pval = P[((size_t)bh*TT + t) * TT + k];
                #pragma unroll
                for (int j = 0; j < 4; j++)
                    acc[i][j] += pval * rv[j5*KC + tx*4 + j];
            }
        }
        float4 o = { acc[i][0], acc[i][1], acc[i][2], acc[i][3] };
        *(float4*)(O + ((size_t)(b*TT + t)) * CC + h*KC + tx*4) = o;
    }
}

// ---------------- fused residual + (optional y-mask) + LayerNorm -----------
__global__ void __launch_bounds__(256)
addln_kernel(const float* __restrict__ X, const float* __restrict__ Y,
             const float* __restrict__ ymask, const float* __restrict__ sc,
             const float* __restrict__ bi, float* __restrict__ Xout)
{
    int row = blockIdx.x;
    int tid = threadIdx.x;
    float m = ymask ? ymask[row] : 1.0f;
    const float* xr = X + (size_t)row * CC;
    const float* yr = Y + (size_t)row * CC;
    float v0 = xr[tid]       + yr[tid]       * m;
    float v1 = xr[tid + 256] + yr[tid + 256] * m;

    __shared__ float red[256];
    red[tid] = v0 + v1; __syncthreads();
    for (int s = 128; s > 0; s >>= 1) {
        if (tid < s) red[tid] += red[tid+s];
        __syncthreads();
    }
    float mean = red[0] * (1.0f / CC);
    __syncthreads();
    float d0 = v0 - mean, d1 = v1 - mean;
    red[tid] = d0*d0 + d1*d1; __syncthreads();
    for (int s = 128; s > 0; s >>= 1) {
        if (tid < s) red[tid] += red[tid+s];
        __syncthreads();
    }
    float r = rsqrtf(red[0] * (1.0f / CC) + 1e-6f);
    Xout[(size_t)row*CC + tid]       = d0 * r * sc[tid]       + bi[tid];
    Xout[(size_t)row*CC + tid + 256] = d1 * r * sc[tid + 256] + bi[tid + 256];
}

// ---------------- host orchestration ---------------------------------------
extern "C" void kernel_launch(void* const* d_in, const int* in_sizes, int n_in,
                              void* d_out, int out_size)
{
    const float* x    = (const float*)d_in[0];
    const float* mask = (const float*)d_in[1];
    const float* Wq   = (const float*)d_in[2];
    const float* bq   = (const float*)d_in[3];
    const float* Wk   = (const float*)d_in[4];
    const float* bk   = (const float*)d_in[5];
    const float* Wv   = (const float*)d_in[6];
    const float* bv   = (const float*)d_in[7];
    const float* Wo   = (const float*)d_in[8];
    const float* bo   = (const float*)d_in[9];
    const float* erk  = (const float*)d_in[10];
    const float* erv  = (const float*)d_in[11];
    const float* ln1s = (const float*)d_in[12];
    const float* ln1b = (const float*)d_in[13];
    const float* W1   = (const float*)d_in[14];
    const float* b1   = (const float*)d_in[15];
    const float* W2   = (const float*)d_in[16];
    const float* b2   = (const float*)d_in[17];
    const float* ln2s = (const float*)d_in[18];
    const float* ln2b = (const float*)d_in[19];
    float* out = (float*)d_out;

    float *px, *pq, *pk, *pvv, *pao, *py, *ph1, *pp;
    cudaGetSymbolAddress((void**)&px,  g_x);
    cudaGetSymbolAddress((void**)&pq,  g_q);
    cudaGetSymbolAddress((void**)&pk,  g_k);
    cudaGetSymbolAddress((void**)&pvv, g_v);
    cudaGetSymbolAddress((void**)&pao, g_ao);
    cudaGetSymbolAddress((void**)&py,  g_y);
    cudaGetSymbolAddress((void**)&ph1, g_h1);
    cudaGetSymbolAddress((void**)&pp,  g_p);

    const int NE = BT * CC;
    maskmul_kernel<<<(NE + 255)/256, 256>>>(x, mask, px, NE);

    dim3 gProj(CC/128, BT/128);   // 4 x 48
    dim3 gFF1 (FF/128, BT/128);   // 16 x 48
    dim3 gFF2 (CC/128, BT/128);
    dim3 gScr (TT/64, TT/64, BB*HH);
    dim3 gPV  (TT/64, BB*HH);

    for (int l = 0; l < LL; l++) {
        const float* Wql = Wq + (size_t)l*CC*CC;  const float* bql = bq + (size_t)l*CC;
        const float* Wkl = Wk + (size_t)l*CC*CC;  const float* bkl = bk + (size_t)l*CC;
        const float* Wvl = Wv + (size_t)l*CC*CC;  const float* bvl = bv + (size_t)l*CC;
        const float* Wol = Wo + (size_t)l*CC*CC;  const float* bol = bo + (size_t)l*CC;
        const float* W1l = W1 + (size_t)l*CC*FF;  const float* b1l = b1 + (size_t)l*FF;
        const float* W2l = W2 + (size_t)l*FF*CC;  const float* b2l = b2 + (size_t)l*CC;
        const float* rkl = erk + (size_t)l*NWIN*KC;
        const float* rvl = erv + (size_t)l*NWIN*KC;

        sgemm_kernel<<<gProj, 256>>>(px, Wql, bql, nullptr, pq,  BT, CC, CC, 0);
        sgemm_kernel<<<gProj, 256>>>(px, Wkl, bkl, nullptr, pk,  BT, CC, CC, 0);
        sgemm_kernel<<<gProj, 256>>>(px, Wvl, bvl, nullptr, pvv, BT, CC, CC, 0);

        scores_kernel<<<gScr, 256>>>(pq, pk, pp);
        softmax_kernel<<<BB*HH*TT, 256>>>(pp, pq, rkl, mask);
        pv_kernel<<<gPV, 256>>>(pp, pvv, rvl, pao);

        sgemm_kernel<<<gProj, 256>>>(pao, Wol, bol, nullptr, py, BT, CC, CC, 0);
        addln_kernel<<<BT, 256>>>(px, py, nullptr, ln1s + (size_t)l*CC, ln1b + (size_t)l*CC, px);

        sgemm_kernel<<<gFF1, 256>>>(px,  W1l, b1l, mask, ph1, BT, FF, CC, 1);
        sgemm_kernel<<<gFF2, 256>>>(ph1, W2l, b2l, mask, py,  BT, CC, FF, 0);
        addln_kernel<<<BT, 256>>>(px, py, mask, ln2s + (size_t)l*CC, ln2b + (size_t)l*CC, px);
    }

    maskmul_kernel<<<(NE + 255)/256, 256>>>(px, mask, out, NE);
}

// round 3
// speedup vs baseline: 1.5333x; 1.5333x over previous
#include <cuda_runtime.h>
#include <cuda_bf16.h>
#include <cstdint>
#include <cstddef>

#define BB   8
#define TT   768
#define CC   512
#define FF   2048
#define HH   8
#define KC   64
#define LL   6
#define BT   (BB*TT)      // 6144
#define NWIN 9

// ---------------- scratch (device globals: allocation-free) ----------------
__device__ float g_x [BT*CC];
__device__ float g_q [BT*CC];
__device__ float g_k [BT*CC];
__device__ float g_v [BT*CC];
__device__ float g_ao[BT*CC];
__device__ float g_y [BT*CC];
__device__ float g_h1[BT*FF];
__device__ float g_p [(size_t)BB*HH*TT*TT];   // 151 MB attention probs
__device__ __nv_bfloat16 g_ahi[(size_t)BT*FF];
__device__ __nv_bfloat16 g_alo[(size_t)BT*FF];
__device__ __nv_bfloat16 g_whi[(size_t)FF*CC];
__device__ __nv_bfloat16 g_wlo[(size_t)FF*CC];

// ======================= baseline-PTX helpers ===============================
static __device__ __forceinline__ uint32_t smem_u32(const void* p) {
    uint32_t a;
    asm("{ .reg .u64 t; cvta.to.shared.u64 t, %1; cvt.u32.u64 %0, t; }" : "=r"(a) : "l"(p));
    return a;
}
#define CP_ASYNC16(saddr, gptr) \
    asm volatile("cp.async.ca.shared.global [%0], [%1], 16;" :: "r"(saddr), "l"(gptr))
#define CP_COMMIT() asm volatile("cp.async.commit_group;")
#define CP_WAIT(n)  asm volatile("cp.async.wait_group %0;" :: "n"(n))

#define LDMX4(r0, r1, r2, r3, addr) \
    asm volatile("ldmatrix.sync.aligned.m8n8.x4.shared.b16 {%0,%1,%2,%3}, [%4];" \
                 : "=r"(r0), "=r"(r1), "=r"(r2), "=r"(r3) : "r"(addr))

#define MMA16816(d, a, b) \
    asm volatile("mma.sync.aligned.m16n8k16.row.col.f32.bf16.bf16.f32 " \
                 "{%0,%1,%2,%3}, {%4,%5,%6,%7}, {%8,%9}, {%0,%1,%2,%3};" \
                 : "+f"((d)[0]), "+f"((d)[1]), "+f"((d)[2]), "+f"((d)[3]) \
                 : "r"((a)[0]), "r"((a)[1]), "r"((a)[2]), "r"((a)[3]), \
                   "r"((b)[0]), "r"((b)[1]))

// ======================= conversion kernels =================================
__global__ void convertA_kernel(const float* __restrict__ X, const float* __restrict__ rowmask,
                                __nv_bfloat16* __restrict__ hi, __nv_bfloat16* __restrict__ lo,
                                int n, int Kc)
{
    int i = (blockIdx.x * 256 + threadIdx.x) * 4;
    if (i >= n) return;
    float4 v = *(const float4*)(X + i);
    if (rowmask) {
        float m = rowmask[i / Kc];
        v.x *= m; v.y *= m; v.z *= m; v.w *= m;
    }
    __nv_bfloat16 h0 = __float2bfloat16(v.x);
    __nv_bfloat16 h1 = __float2bfloat16(v.y);
    __nv_bfloat16 h2 = __float2bfloat16(v.z);
    __nv_bfloat16 h3 = __float2bfloat16(v.w);
    __nv_bfloat16 l0 = __float2bfloat16(v.x - __bfloat162float(h0));
    __nv_bfloat16 l1 = __float2bfloat16(v.y - __bfloat162float(h1));
    __nv_bfloat16 l2 = __float2bfloat16(v.z - __bfloat162float(h2));
    __nv_bfloat16 l3 = __float2bfloat16(v.w - __bfloat162float(h3));
    *(__nv_bfloat162*)(hi + i)     = __halves2bfloat162(h0, h1);
    *(__nv_bfloat162*)(hi + i + 2) = __halves2bfloat162(h2, h3);
    *(__nv_bfloat162*)(lo + i)     = __halves2bfloat162(l0, l1);
    *(__nv_bfloat162*)(lo + i + 2) = __halves2bfloat162(l2, l3);
}

// W [K,N] fp32 -> Wt [N,K] bf16 hi/lo (transpose + split)
__global__ void convertWt_kernel(const float* __restrict__ W,
                                 __nv_bfloat16* __restrict__ hi, __nv_bfloat16* __restrict__ lo,
                                 int K, int N)
{
    __shared__ float t[32][33];
    int n0 = blockIdx.x * 32, k0 = blockIdx.y * 32;
    int tx = threadIdx.x, ty = threadIdx.y;   // 32 x 8
    #pragma unroll
    for (int r = 0; r < 32; r += 8)
        t[ty + r][tx] = W[(size_t)(k0 + ty + r) * N + n0 + tx];
    __syncthreads();
    #pragma unroll
    for (int r = 0; r < 32; r += 8) {
        float v = t[tx][ty + r];
        __nv_bfloat16 h = __float2bfloat16(v);
        size_t o = (size_t)(n0 + ty + r) * K + k0 + tx;
        hi[o] = h;
        lo[o] = __float2bfloat16(v - __bfloat162float(h));
    }
}

// ======================= tensor-core GEMM (mma.sync bf16) ===================
// C[M,N] = (aHi+aLo)[M,K] @ (bHi+bLo)[N,K]^T + bias  (split-bf16 3-product)
// Tile 128x128, BK=32, 256 thr, warps 2(M)x4(N), 80B smem row stride
#define LDT     40          // bf16 elems per smem row (80 bytes)
#define TILEB   (128*80)    // 10240 B per tile
#define STAGEB  (4*TILEB)   // Ah, Al, Bh, Bl
#define DSMEM   (2*STAGEB)  // 81920 B

__global__ void __launch_bounds__(256, 1)
mma_gemm_kernel(const __nv_bfloat16* __restrict__ aHi, const __nv_bfloat16* __restrict__ aLo,
                const __nv_bfloat16* __restrict__ bHi, const __nv_bfloat16* __restrict__ bLo,
                const float* __restrict__ bias, float* __restrict__ C,
                int M, int N, int K, int relu)
{
    extern __shared__ unsigned char dsm[];
    const int tid  = threadIdx.x;
    const int lane = tid & 31, warp = tid >> 5;
    const int wm = warp >> 2, wn = warp & 3;     // 2 x 4 warp grid
    const int bm = blockIdx.y * 128;
    const int bn = blockIdx.x * 128;
    const uint32_t sbase = smem_u32(dsm);

    float acc[4][4][4];
    #pragma unroll
    for (int i = 0; i < 4; i++)
        #pragma unroll
        for (int j = 0; j < 4; j++)
            #pragma unroll
            for (int e = 0; e < 4; e++) acc[i][j][e] = 0.f;

    const int nk = K >> 5;   // K/32 stages

    auto load_stage = [&](int kt, int s) {
        const int kt0 = kt << 5;
        uint32_t sst = sbase + s * STAGEB;
        #pragma unroll
        for (int t = 0; t < 4; t++) {
            const __nv_bfloat16* src = (t == 0) ? aHi : (t == 1) ? aLo : (t == 2) ? bHi : bLo;
            const int r0 = (t < 2) ? bm : bn;
            uint32_t stile = sst + t * TILEB;
            #pragma unroll
            for (int u = 0; u < 2; u++) {
                int c = u * 256 + tid;          // 0..511 chunk id
                int row = c >> 2, col = (c & 3) * 8;
                const __nv_bfloat16* g = src + (size_t)(r0 + row) * K + kt0 + col;
                CP_ASYNC16(stile + row * 80 + col * 2, g);
            }
        }
    };

    load_stage(0, 0);
    CP_COMMIT();

    int buf = 0;
    for (int kt = 0; kt < nk; kt++) {
        if (kt + 1 < nk) {
            load_stage(kt + 1, buf ^ 1);
            CP_COMMIT();
            CP_WAIT(1);
        } else {
            CP_WAIT(0);
        }
        __syncthreads();

        uint32_t sAh = sbase + buf * STAGEB;
        uint32_t sAl = sAh + TILEB;
        uint32_t sBh = sAh + 2 * TILEB;
        uint32_t sBl = sAh + 3 * TILEB;

        #pragma unroll
        for (int ks = 0; ks < 32; ks += 16) {
            uint32_t Ah[4][4], Al[4][4], Bh[4][2], Bl[4][2];
            // A fragments: row = wm*64 + i*16 + (lane&15), col = (lane>>4)*8 + ks
            #pragma unroll
            for (int i = 0; i < 4; i++) {
                uint32_t off = (uint32_t)((wm * 64 + i * 16 + (lane & 15)) * 80
                                          + ((lane >> 4) * 8 + ks) * 2);
                LDMX4(Ah[i][0], Ah[i][1], Ah[i][2], Ah[i][3], sAh + off);
                LDMX4(Al[i][0], Al[i][1], Al[i][2], Al[i][3], sAl + off);
            }
            // B fragments: sub = lane>>3; row = (lane&7)+(sub>>1)*8; kcol=(sub&1)*8+ks
            #pragma unroll
            for (int p = 0; p < 2; p++) {
                int sub = lane >> 3;
                uint32_t off = (uint32_t)((wn * 32 + p * 16 + (lane & 7) + (sub >> 1) * 8) * 80
                                          + ((sub & 1) * 8 + ks) * 2);
                LDMX4(Bh[2*p][0], Bh[2*p][1], Bh[2*p+1][0], Bh[2*p+1][1], sBh + off);
                LDMX4(Bl[2*p][0], Bl[2*p][1], Bl[2*p+1][0], Bl[2*p+1][1], sBl + off);
            }
            // hi*hi
            #pragma unroll
            for (int i = 0; i < 4; i++)
                #pragma unroll
                for (int j = 0; j < 4; j++)
                    MMA16816(acc[i][j], Ah[i], Bh[j]);
            // lo*hi
            #pragma unroll
            for (int i = 0; i < 4; i++)
                #pragma unroll
                for (int j = 0; j < 4; j++)
                    MMA16816(acc[i][j], Al[i], Bh[j]);
            // hi*lo
            #pragma unroll
            for (int i = 0; i < 4; i++)
                #pragma unroll
                for (int j = 0; j < 4; j++)
                    MMA16816(acc[i][j], Ah[i], Bl[j]);
        }
        __syncthreads();
        buf ^= 1;
    }

    // epilogue
    #pragma unroll
    for (int i = 0; i < 4; i++) {
        int r = bm + wm * 64 + i * 16 + (lane >> 2);
        #pragma unroll
        for (int j = 0; j < 4; j++) {
            int cix = bn + wn * 32 + j * 8 + (lane & 3) * 2;
            float b0 = bias[cix], b1 = bias[cix + 1];
            float2 v0 = { acc[i][j][0] + b0, acc[i][j][1] + b1 };
            float2 v1 = { acc[i][j][2] + b0, acc[i][j][3] + b1 };
            if (relu) {
                v0.x = fmaxf(v0.x, 0.f); v0.y = fmaxf(v0.y, 0.f);
                v1.x = fmaxf(v1.x, 0.f); v1.y = fmaxf(v1.y, 0.f);
            }
            *(float2*)(C + (size_t)r * N + cix)       = v0;
            *(float2*)(C + (size_t)(r + 8) * N + cix) = v1;
        }
    }
}

// ---------------- elementwise: out[i] = in[i] * mask[row] ------------------
__global__ void maskmul_kernel(const float* __restrict__ in,
                               const float* __restrict__ mask,
                               float* __restrict__ out, int n)
{
    int i = blockIdx.x * blockDim.x + threadIdx.x;
    if (i < n) out[i] = in[i] * mask[i / CC];
}

// ---------------- scores[b,h,i,j] = scale * <Q_i, K_j> ---------------------
__global__ void __launch_bounds__(256)
scores_kernel(const float* __restrict__ Q, const float* __restrict__ Km,
              float* __restrict__ P)
{
    __shared__ float Qs[64][65];
    __shared__ float Ks[64][65];
    int tid = threadIdx.x;
    int bh = blockIdx.z;
    int b = bh >> 3, h = bh & 7;
    int ti0 = blockIdx.y * 64, tj0 = blockIdx.x * 64;
    int lr = tid >> 4, lc = (tid & 15) * 4;

    const float* qbase = Q + ((size_t)(b*TT + ti0)) * CC + h*KC;
    const float* kbase = Km + ((size_t)(b*TT + tj0)) * CC + h*KC;
    #pragma unroll
    for (int rr = 0; rr < 64; rr += 16) {
        float4 qv = *(const float4*)(qbase + (size_t)(lr+rr)*CC + lc);
        Qs[lr+rr][lc+0]=qv.x; Qs[lr+rr][lc+1]=qv.y; Qs[lr+rr][lc+2]=qv.z; Qs[lr+rr][lc+3]=qv.w;
        float4 kv = *(const float4*)(kbase + (size_t)(lr+rr)*CC + lc);
        Ks[lr+rr][lc+0]=kv.x; Ks[lr+rr][lc+1]=kv.y; Ks[lr+rr][lc+2]=kv.z; Ks[lr+rr][lc+3]=kv.w;
    }
    __syncthreads();

    int tx = tid & 15, ty = tid >> 4;
    float acc[4][4];
    #pragma unroll
    for (int i=0;i<4;i++) { acc[i][0]=0;acc[i][1]=0;acc[i][2]=0;acc[i][3]=0; }

    #pragma unroll 4
    for (int d = 0; d < 64; d++) {
        float qr[4], kr[4];
        #pragma unroll
        for (int i = 0; i < 4; i++) qr[i] = Qs[ty*4+i][d];
        #pragma unroll
        for (int j = 0; j < 4; j++) kr[j] = Ks[tx*4+j][d];
        #pragma unroll
        for (int i = 0; i < 4; i++)
            #pragma unroll
            for (int j = 0; j < 4; j++)
                acc[i][j] += qr[i] * kr[j];
    }
    const float scale = 0.125f;
    #pragma unroll
    for (int i = 0; i < 4; i++) {
        float4 o = { acc[i][0]*scale, acc[i][1]*scale, acc[i][2]*scale, acc[i][3]*scale };
        *(float4*)(P + ((size_t)bh*TT + ti0 + ty*4 + i) * TT + tj0 + tx*4) = o;
    }
}

// ---------------- fused rel-band + mask + softmax (in-place on P) ----------
__global__ void __launch_bounds__(256)
softmax_kernel(float* __restrict__ P, const float* __restrict__ Q,
               const float* __restrict__ rk, const float* __restrict__ mask)
{
    int row = blockIdx.x;
    int qi  = row % TT;
    int bh  = row / TT;
    int b = bh >> 3, h = bh & 7;
    int tid = threadIdx.x;

    __shared__ float rel9[NWIN];
    __shared__ float red[256];

    if (tid < NWIN) {
        const float* qv  = Q + ((size_t)(b*TT + qi)) * CC + h*KC;
        const float* rkj = rk + tid * KC;
        float s = 0.f;
        #pragma unroll 8
        for (int d = 0; d < KC; d++) s += qv[d] * rkj[d];
        rel9[tid] = s * 0.125f;
    }
    __syncthreads();

    float mq = mask[b*TT + qi];
    float* prow = P + (size_t)row * TT;
    float vals[3];
    float mx = -1e30f;
    #pragma unroll
    for (int u = 0; u < 3; u++) {
        int k = tid + u*256;
        float s = prow[k];
        int j = k - qi + 4;
        if ((unsigned)j < (unsigned)NWIN) s += rel9[j];
        if (mq * mask[b*TT + k] == 0.f) s = -10000.f;
        vals[u] = s;
        mx = fmaxf(mx, s);
    }
    red[tid] = mx; __syncthreads();
    for (int s = 128; s > 0; s >>= 1) {
        if (tid < s) red[tid] = fmaxf(red[tid], red[tid+s]);
        __syncthreads();
    }
    mx = red[0]; __syncthreads();

    float sum = 0.f;
    #pragma unroll
    for (int u = 0; u < 3; u++) { vals[u] = expf(vals[u] - mx); sum += vals[u]; }
    red[tid] = sum; __syncthreads();
    for (int s = 128; s > 0; s >>= 1) {
        if (tid < s) red[tid] += red[tid+s];
        __syncthreads();
    }
    float inv = 1.f / red[0];
    #pragma unroll
    for (int u = 0; u < 3; u++) prow[tid + u*256] = vals[u] * inv;
}

// ---------------- O = P @ V (+ rel_v band), written as [B,T,C] -------------
__global__ void __launch_bounds__(256)
pv_kernel(const float* __restrict__ P, const float* __restrict__ V,
          const float* __restrict__ rv, float* __restrict__ O)
{
    __shared__ float Ps[64][65];
    __shared__ float Vs[64][65];
    int tid = threadIdx.x;
    int bh = blockIdx.y;
    int b = bh >> 3, h = bh & 7;
    int ti0 = blockIdx.x * 64;
    int lr = tid >> 4, lc = (tid & 15) * 4;
    int tx = tid & 15, ty = tid >> 4;

    float acc[4][4];
    #pragma unroll
    for (int i=0;i<4;i++) { acc[i][0]=0;acc[i][1]=0;acc[i][2]=0;acc[i][3]=0; }

    for (int kk = 0; kk < TT; kk += 64) {
        #pragma unroll
        for (int rr = 0; rr < 64; rr += 16) {
            float4 p4 = *(const float4*)(P + ((size_t)bh*TT + ti0 + lr+rr) * TT + kk + lc);
            Ps[lr+rr][lc+0]=p4.x; Ps[lr+rr][lc+1]=p4.y; Ps[lr+rr][lc+2]=p4.z; Ps[lr+rr][lc+3]=p4.w;
            float4 v4 = *(const float4*)(V + ((size_t)(b*TT + kk + lr+rr)) * CC + h*KC + lc);
            Vs[lr+rr][lc+0]=v4.x; Vs[lr+rr][lc+1]=v4.y; Vs[lr+rr][lc+2]=v4.z; Vs[lr+rr][lc+3]=v4.w;
        }
        __syncthreads();
        #pragma unroll 4
        for (int k = 0; k < 64; k++) {
            float pr[4], vr[4];
            #pragma unroll
            for (int i = 0; i < 4; i++) pr[i] = Ps[ty*4+i][k];
            #pragma unroll
            for (int j = 0; j < 4; j++) vr[j] = Vs[k][tx*4+j];
            #pragma unroll
            for (int i = 0; i < 4; i++)
                #pragma unroll
                for (int j = 0; j < 4; j++)
                    acc[i][j] += pr[i] * vr[j];
        }
        __syncthreads();
    }

    #pragma unroll
    for (int i = 0; i < 4; i++) {
        int t = ti0 + ty*4 + i;
        #pragma unroll
        for (int j5 = 0; j5 < NWIN; j5++) {
            int k = t + j5 - 4;
            if (k >= 0 && k < TT) {
                float pval = P[((size_t)bh*TT + t) * TT + k];
                #pragma unroll
                for (int j = 0; j < 4; j++)
                    acc[i][j] += pval * rv[j5*KC + tx*4 + j];
            }
        }
        float4 o = { acc[i][0], acc[i][1], acc[i][2], acc[i][3] };
        *(float4*)(O + ((size_t)(b*TT + t)) * CC + h*KC + tx*4) = o;
    }
}

// ---------------- fused residual + (optional y-mask) + LayerNorm -----------
__global__ void __launch_bounds__(256)
addln_kernel(const float* __restrict__ X, const float* __restrict__ Y,
             const float* __restrict__ ymask, const float* __restrict__ sc,
             const float* __restrict__ bi, float* __restrict__ Xout)
{
    int row = blockIdx.x;
    int tid = threadIdx.x;
    float m = ymask ? ymask[row] : 1.0f;
    const float* xr = X + (size_t)row * CC;
    const float* yr = Y + (size_t)row * CC;
    float v0 = xr[tid]       + yr[tid]       * m;
    float v1 = xr[tid + 256] + yr[tid + 256] * m;

    __shared__ float red[256];
    red[tid] = v0 + v1; __syncthreads();
    for (int s = 128; s > 0; s >>= 1) {
        if (tid < s) red[tid] += red[tid+s];
        __syncthreads();
    }
    float mean = red[0] * (1.0f / CC);
    __syncthreads();
    float d0 = v0 - mean, d1 = v1 - mean;
    red[tid] = d0*d0 + d1*d1; __syncthreads();
    for (int s = 128; s > 0; s >>= 1) {
        if (tid < s) red[tid] += red[tid+s];
        __syncthreads();
    }
    float r = rsqrtf(red[0] * (1.0f / CC) + 1e-6f);
    Xout[(size_t)row*CC + tid]       = d0 * r * sc[tid]       + bi[tid];
    Xout[(size_t)row*CC + tid + 256] = d1 * r * sc[tid + 256] + bi[tid + 256];
}

// ---------------- host orchestration ---------------------------------------
extern "C" void kernel_launch(void* const* d_in, const int* in_sizes, int n_in,
                              void* d_out, int out_size)
{
    const float* x    = (const float*)d_in[0];
    const float* mask = (const float*)d_in[1];
    const float* Wq   = (const float*)d_in[2];
    const float* bq   = (const float*)d_in[3];
    const float* Wk   = (const float*)d_in[4];
    const float* bk   = (const float*)d_in[5];
    const float* Wv   = (const float*)d_in[6];
    const float* bv   = (const float*)d_in[7];
    const float* Wo   = (const float*)d_in[8];
    const float* bo   = (const float*)d_in[9];
    const float* erk  = (const float*)d_in[10];
    const float* erv  = (const float*)d_in[11];
    const float* ln1s = (const float*)d_in[12];
    const float* ln1b = (const float*)d_in[13];
    const float* W1   = (const float*)d_in[14];
    const float* b1   = (const float*)d_in[15];
    const float* W2   = (const float*)d_in[16];
    const float* b2   = (const float*)d_in[17];
    const float* ln2s = (const float*)d_in[18];
    const float* ln2b = (const float*)d_in[19];
    float* out = (float*)d_out;

    float *px, *pq, *pk, *pvv, *pao, *py, *ph1, *pp;
    __nv_bfloat16 *ahi, *alo, *whi, *wlo;
    cudaGetSymbolAddress((void**)&px,  g_x);
    cudaGetSymbolAddress((void**)&pq,  g_q);
    cudaGetSymbolAddress((void**)&pk,  g_k);
    cudaGetSymbolAddress((void**)&pvv, g_v);
    cudaGetSymbolAddress((void**)&pao, g_ao);
    cudaGetSymbolAddress((void**)&py,  g_y);
    cudaGetSymbolAddress((void**)&ph1, g_h1);
    cudaGetSymbolAddress((void**)&pp,  g_p);
    cudaGetSymbolAddress((void**)&ahi, g_ahi);
    cudaGetSymbolAddress((void**)&alo, g_alo);
    cudaGetSymbolAddress((void**)&whi, g_whi);
    cudaGetSymbolAddress((void**)&wlo, g_wlo);

    cudaFuncSetAttribute(mma_gemm_kernel, cudaFuncAttributeMaxDynamicSharedMemorySize, DSMEM);

    const int NE = BT * CC;
    maskmul_kernel<<<(NE + 255)/256, 256>>>(x, mask, px, NE);

    dim3 gGemmC(CC/128, BT/128);   // N=512
    dim3 gGemmF(FF/128, BT/128);   // N=2048
    dim3 gWc(CC/32, CC/32);
    dim3 gW1(FF/32, CC/32);
    dim3 gW2(CC/32, FF/32);
    dim3 blkW(32, 8);
    dim3 gScr(TT/64, TT/64, BB*HH);
    dim3 gPV (TT/64, BB*HH);
    const int cA_C = (BT*CC/4 + 255)/256;
    const int cA_F = (BT*FF/4 + 255)/256;

    for (int l = 0; l < LL; l++) {
        const float* Wql = Wq + (size_t)l*CC*CC;  const float* bql = bq + (size_t)l*CC;
        const float* Wkl = Wk + (size_t)l*CC*CC;  const float* bkl = bk + (size_t)l*CC;
        const float* Wvl = Wv + (size_t)l*CC*CC;  const float* bvl = bv + (size_t)l*CC;
        const float* Wol = Wo + (size_t)l*CC*CC;  const float* bol = bo + (size_t)l*CC;
        const float* W1l = W1 + (size_t)l*CC*FF;  const float* b1l = b1 + (size_t)l*FF;
        const float* W2l = W2 + (size_t)l*FF*CC;  const float* b2l = b2 + (size_t)l*CC;
        const float* rkl = erk + (size_t)l*NWIN*KC;
        const float* rvl = erv + (size_t)l*NWIN*KC;

        // --- QKV projections (shared A conversion) ---
        convertA_kernel<<<cA_C, 256>>>(px, nullptr, ahi, alo, BT*CC, CC);
        convertWt_kernel<<<gWc, blkW>>>(Wql, whi, wlo, CC, CC);
        mma_gemm_kernel<<<gGemmC, 256, DSMEM>>>(ahi, alo, whi, wlo, bql, pq,  BT, CC, CC, 0);
        convertWt_kernel<<<gWc, blkW>>>(Wkl, whi, wlo, CC, CC);
        mma_gemm_kernel<<<gGemmC, 256, DSMEM>>>(ahi, alo, whi, wlo, bkl, pk,  BT, CC, CC, 0);
        convertWt_kernel<<<gWc, blkW>>>(Wvl, whi, wlo, CC, CC);
        mma_gemm_kernel<<<gGemmC, 256, DSMEM>>>(ahi, alo, whi, wlo, bvl, pvv, BT, CC, CC, 0);

        // --- attention ---
        scores_kernel<<<gScr, 256>>>(pq, pk, pp);
        softmax_kernel<<<BB*HH*TT, 256>>>(pp, pq, rkl, mask);
        pv_kernel<<<gPV, 256>>>(pp, pvv, rvl, pao);

        // --- output projection ---
        convertA_kernel<<<cA_C, 256>>>(pao, nullptr, ahi, alo, BT*CC, CC);
        convertWt_kernel<<<gWc, blkW>>>(Wol, whi, wlo, CC, CC);
        mma_gemm_kernel<<<gGemmC, 256, DSMEM>>>(ahi, alo, whi, wlo, bol, py, BT, CC, CC, 0);
        addln_kernel<<<BT, 256>>>(px, py, nullptr, ln1s + (size_t)l*CC, ln1b + (size_t)l*CC, px);

        // --- FFN ---
        convertA_kernel<<<cA_C, 256>>>(px, mask, ahi, alo, BT*CC, CC);
        convertWt_kernel<<<gW1, blkW>>>(W1l, whi, wlo, CC, FF);
        mma_gemm_kernel<<<gGemmF, 256, DSMEM>>>(ahi, alo, whi, wlo, b1l, ph1, BT, FF, CC, 1);
        convertA_kernel<<<cA_F, 256>>>(ph1, mask, ahi, alo, BT*FF, FF);
        convertWt_kernel<<<gW2, blkW>>>(W2l, whi, wlo, FF, CC);
        mma_gemm_kernel<<<gGemmC, 256, DSMEM>>>(ahi, alo, whi, wlo, b2l, py, BT, CC, FF, 0);
        addln_kernel<<<BT, 256>>>(px, py, mask, ln2s + (size_t)l*CC, ln2b + (size_t)l*CC, px);
    }

    maskmul_kernel<<<(NE + 255)/256, 256>>>(px, mask, out, NE);
}

// round 4
// speedup vs baseline: 2.1472x; 1.4004x over previous
#include <cuda_runtime.h>
#include <cuda_bf16.h>
#include <cstdint>
#include <cstddef>

#define BB   8
#define TT   768
#define CC   512
#define FF   2048
#define HH   8
#define KC   64
#define LL   6
#define BT   (BB*TT)      // 6144
#define QKVC (3*CC)       // 1536
#define NWIN 9

// ---------------- scratch (device globals: allocation-free) ----------------
__device__ float g_x [BT*CC];
__device__ float g_y [BT*CC];
__device__ float g_p [(size_t)BB*HH*TT*TT];      // fp32 logits
__device__ float g_bias[QKVC];
__device__ __nv_bfloat16 g_xhi [BT*CC];
__device__ __nv_bfloat16 g_xlo [BT*CC];
__device__ __nv_bfloat16 g_qkvhi[(size_t)BT*QKVC];
__device__ __nv_bfloat16 g_qkvlo[(size_t)BT*QKVC];
__device__ __nv_bfloat16 g_phi[(size_t)BB*HH*TT*TT];
__device__ __nv_bfloat16 g_plo[(size_t)BB*HH*TT*TT];
__device__ __nv_bfloat16 g_paohi[BT*CC];
__device__ __nv_bfloat16 g_paolo[BT*CC];
__device__ __nv_bfloat16 g_h1hi[(size_t)BT*FF];
__device__ __nv_bfloat16 g_h1lo[(size_t)BT*FF];
__device__ __nv_bfloat16 g_whi[(size_t)FF*CC];
__device__ __nv_bfloat16 g_wlo[(size_t)FF*CC];

// ======================= baseline-PTX helpers ===============================
static __device__ __forceinline__ uint32_t smem_u32(const void* p) {
    uint32_t a;
    asm("{ .reg .u64 t; cvta.to.shared.u64 t, %1; cvt.u32.u64 %0, t; }" : "=r"(a) : "l"(p));
    return a;
}
#define CP_ASYNC16(saddr, gptr) \
    asm volatile("cp.async.ca.shared.global [%0], [%1], 16;" :: "r"(saddr), "l"(gptr))
#define CP_COMMIT() asm volatile("cp.async.commit_group;")
#define CP_WAIT(n)  asm volatile("cp.async.wait_group %0;" :: "n"(n))

#define LDMX4(r0, r1, r2, r3, addr) \
    asm volatile("ldmatrix.sync.aligned.m8n8.x4.shared.b16 {%0,%1,%2,%3}, [%4];" \
                 : "=r"(r0), "=r"(r1), "=r"(r2), "=r"(r3) : "r"(addr))
#define LDMX4T(r0, r1, r2, r3, addr) \
    asm volatile("ldmatrix.sync.aligned.m8n8.x4.trans.shared.b16 {%0,%1,%2,%3}, [%4];" \
                 : "=r"(r0), "=r"(r1), "=r"(r2), "=r"(r3) : "r"(addr))

#define MMA16816(d, a, b) \
    asm volatile("mma.sync.aligned.m16n8k16.row.col.f32.bf16.bf16.f32 " \
                 "{%0,%1,%2,%3}, {%4,%5,%6,%7}, {%8,%9}, {%0,%1,%2,%3};" \
                 : "+f"((d)[0]), "+f"((d)[1]), "+f"((d)[2]), "+f"((d)[3]) \
                 : "r"((a)[0]), "r"((a)[1]), "r"((a)[2]), "r"((a)[3]), \
                   "r"((b)[0]), "r"((b)[1]))

static __device__ __forceinline__ void split_bf16(float v, __nv_bfloat16& h, __nv_bfloat16& l) {
    h = __float2bfloat16(v);
    l = __float2bfloat16(v - __bfloat162float(h));
}

// ======================= small utility kernels ==============================
__global__ void init_kernel(const float* __restrict__ X, const float* __restrict__ mask,
                            float* __restrict__ Xo,
                            __nv_bfloat16* __restrict__ hi, __nv_bfloat16* __restrict__ lo)
{
    int i = blockIdx.x * 256 + threadIdx.x;
    if (i >= BT*CC) return;
    float v = X[i] * mask[i / CC];
    Xo[i] = v;
    __nv_bfloat16 h, l; split_bf16(v, h, l);
    hi[i] = h; lo[i] = l;
}

__global__ void maskmul_kernel(const float* __restrict__ in, const float* __restrict__ mask,
                               float* __restrict__ out, int n)
{
    int i = blockIdx.x * 256 + threadIdx.x;
    if (i < n) out[i] = in[i] * mask[i / CC];
}

__global__ void packbias_kernel(const float* __restrict__ bq, const float* __restrict__ bk,
                                const float* __restrict__ bv, float* __restrict__ dst)
{
    int i = blockIdx.x * 256 + threadIdx.x;
    if (i >= QKVC) return;
    dst[i] = (i < CC) ? bq[i] : (i < 2*CC) ? bk[i - CC] : bv[i - 2*CC];
}

// W [K,N] fp32 -> Wt [N,K] bf16 hi/lo (transpose + split)
__global__ void convertWt_kernel(const float* __restrict__ W,
                                 __nv_bfloat16* __restrict__ hi, __nv_bfloat16* __restrict__ lo,
                                 int K, int N)
{
    __shared__ float t[32][33];
    int n0 = blockIdx.x * 32, k0 = blockIdx.y * 32;
    int tx = threadIdx.x, ty = threadIdx.y;   // 32 x 8
    #pragma unroll
    for (int r = 0; r < 32; r += 8)
        t[ty + r][tx] = W[(size_t)(k0 + ty + r) * N + n0 + tx];
    __syncthreads();
    #pragma unroll
    for (int r = 0; r < 32; r += 8) {
        float v = t[tx][ty + r];
        __nv_bfloat16 h, l; split_bf16(v, h, l);
        size_t o = (size_t)(n0 + ty + r) * K + k0 + tx;
        hi[o] = h; lo[o] = l;
    }
}

// ======================= dense tensor-core GEMM =============================
// C[M,N] = (aHi+aLo)[M,K] @ (bHi+bLo)[N,K]^T + bias  (split-bf16 3-product)
// Optional outputs: fp32 C, and/or bf16 hi/lo split (with relu + rowmask).
#define TILEB   (128*80)
#define STAGEB  (4*TILEB)
#define DSMEM_G (2*STAGEB)

__global__ void __launch_bounds__(256, 1)
mma_gemm_kernel(const __nv_bfloat16* __restrict__ aHi, const __nv_bfloat16* __restrict__ aLo,
                const __nv_bfloat16* __restrict__ bHi, const __nv_bfloat16* __restrict__ bLo,
                const float* __restrict__ bias, float* __restrict__ C,
                __nv_bfloat16* __restrict__ Chi, __nv_bfloat16* __restrict__ Clo,
                const float* __restrict__ rowmask,
                int M, int N, int K, int relu)
{
    extern __shared__ unsigned char dsm[];
    const int tid  = threadIdx.x;
    const int lane = tid & 31, warp = tid >> 5;
    const int wm = warp >> 2, wn = warp & 3;
    const int bm = blockIdx.y * 128;
    const int bn = blockIdx.x * 128;
    const uint32_t sbase = smem_u32(dsm);

    float acc[4][4][4];
    #pragma unroll
    for (int i = 0; i < 4; i++)
        #pragma unroll
        for (int j = 0; j < 4; j++)
            #pragma unroll
            for (int e = 0; e < 4; e++) acc[i][j][e] = 0.f;

    const int nk = K >> 5;

    auto load_stage = [&](int kt, int s) {
        const int kt0 = kt << 5;
        uint32_t sst = sbase + s * STAGEB;
        #pragma unroll
        for (int t = 0; t < 4; t++) {
            const __nv_bfloat16* src = (t == 0) ? aHi : (t == 1) ? aLo : (t == 2) ? bHi : bLo;
            const int r0 = (t < 2) ? bm : bn;
            uint32_t stile = sst + t * TILEB;
            #pragma unroll
            for (int u = 0; u < 2; u++) {
                int c = u * 256 + tid;
                int row = c >> 2, col = (c & 3) * 8;
                const __nv_bfloat16* g = src + (size_t)(r0 + row) * K + kt0 + col;
                CP_ASYNC16(stile + row * 80 + col * 2, g);
            }
        }
    };

    load_stage(0, 0);
    CP_COMMIT();

    int buf = 0;
    for (int kt = 0; kt < nk; kt++) {
        if (kt + 1 < nk) { load_stage(kt + 1, buf ^ 1); CP_COMMIT(); CP_WAIT(1); }
        else             { CP_WAIT(0); }
        __syncthreads();

        uint32_t sAh = sbase + buf * STAGEB;
        uint32_t sAl = sAh + TILEB;
        uint32_t sBh = sAh + 2 * TILEB;
        uint32_t sBl = sAh + 3 * TILEB;

        #pragma unroll
        for (int ks = 0; ks < 32; ks += 16) {
            uint32_t Ah[4][4], Al[4][4], Bh[4][2], Bl[4][2];
            #pragma unroll
            for (int i = 0; i < 4; i++) {
                uint32_t off = (uint32_t)((wm * 64 + i * 16 + (lane & 15)) * 80
                                          + ((lane >> 4) * 8 + ks) * 2);
                LDMX4(Ah[i][0], Ah[i][1], Ah[i][2], Ah[i][3], sAh + off);
                LDMX4(Al[i][0], Al[i][1], Al[i][2], Al[i][3], sAl + off);
            }
            #pragma unroll
            for (int p = 0; p < 2; p++) {
                int sub = lane >> 3;
                uint32_t off = (uint32_t)((wn * 32 + p * 16 + (lane & 7) + (sub >> 1) * 8) * 80
                                          + ((sub & 1) * 8 + ks) * 2);
                LDMX4(Bh[2*p][0], Bh[2*p][1], Bh[2*p+1][0], Bh[2*p+1][1], sBh + off);
                LDMX4(Bl[2*p][0], Bl[2*p][1], Bl[2*p+1][0], Bl[2*p+1][1], sBl + off);
            }
            #pragma unroll
            for (int i = 0; i < 4; i++)
                #pragma unroll
                for (int j = 0; j < 4; j++)
                    MMA16816(acc[i][j], Ah[i], Bh[j]);
            #pragma unroll
            for (int i = 0; i < 4; i++)
                #pragma unroll
                for (int j = 0; j < 4; j++)
                    MMA16816(acc[i][j], Al[i], Bh[j]);
            #pragma unroll
            for (int i = 0; i < 4; i++)
                #pragma unroll
                for (int j = 0; j < 4; j++)
                    MMA16816(acc[i][j], Ah[i], Bl[j]);
        }
        __syncthreads();
        buf ^= 1;
    }

    #pragma unroll
    for (int i = 0; i < 4; i++) {
        int r = bm + wm * 64 + i * 16 + (lane >> 2);
        float m0 = rowmask ? rowmask[r]     : 1.f;
        float m1 = rowmask ? rowmask[r + 8] : 1.f;
        #pragma unroll
        for (int j = 0; j < 4; j++) {
            int cix = bn + wn * 32 + j * 8 + (lane & 3) * 2;
            float b0 = bias[cix], b1 = bias[cix + 1];
            float v[4];
            v[0] = acc[i][j][0] + b0; v[1] = acc[i][j][1] + b1;
            v[2] = acc[i][j][2] + b0; v[3] = acc[i][j][3] + b1;
            if (relu) {
                #pragma unroll
                for (int e = 0; e < 4; e++) v[e] = fmaxf(v[e], 0.f);
            }
            v[0] *= m0; v[1] *= m0; v[2] *= m1; v[3] *= m1;
            if (C) {
                *(float2*)(C + (size_t)r * N + cix)       = make_float2(v[0], v[1]);
                *(float2*)(C + (size_t)(r + 8) * N + cix) = make_float2(v[2], v[3]);
            }
            if (Chi) {
                __nv_bfloat16 h0, l0, h1, l1;
                split_bf16(v[0], h0, l0); split_bf16(v[1], h1, l1);
                *(__nv_bfloat162*)(Chi + (size_t)r * N + cix) = __halves2bfloat162(h0, h1);
                *(__nv_bfloat162*)(Clo + (size_t)r * N + cix) = __halves2bfloat162(l0, l1);
                split_bf16(v[2], h0, l0); split_bf16(v[3], h1, l1);
                *(__nv_bfloat162*)(Chi + (size_t)(r + 8) * N + cix) = __halves2bfloat162(h0, h1);
                *(__nv_bfloat162*)(Clo + (size_t)(r + 8) * N + cix) = __halves2bfloat162(l0, l1);
            }
        }
    }
}

// ======================= scores via mma (split-bf16) ========================
// P[bh, i, j] = 0.125 * <q_i, k_j>.  Tile 128x128, K=64 (single stage).
#define SLDT    72
#define STILE_S (128*SLDT*2)       // 18432 B per tile
#define DSMEM_S (4*STILE_S)        // 73728

__global__ void __launch_bounds__(256, 1)
scores_mma_kernel(const __nv_bfloat16* __restrict__ qkvh, const __nv_bfloat16* __restrict__ qkvl,
                  float* __restrict__ P)
{
    extern __shared__ unsigned char dsm[];
    const int tid  = threadIdx.x;
    const int lane = tid & 31, warp = tid >> 5;
    const int wm = warp >> 2, wn = warp & 3;
    const int bh = blockIdx.z, b = bh >> 3, h = bh & 7;
    const int i0 = blockIdx.y * 128, j0 = blockIdx.x * 128;
    const uint32_t sbase = smem_u32(dsm);

    // tiles: 0=Qh 1=Ql 2=Kh 3=Kl
    #pragma unroll
    for (int t = 0; t < 4; t++) {
        const __nv_bfloat16* src = (t & 1) ? qkvl : qkvh;
        const int r0 = (t < 2) ? i0 : j0;
        const int coff = (t < 2) ? h * KC : CC + h * KC;
        uint32_t stile = sbase + t * STILE_S;
        #pragma unroll
        for (int u = 0; u < 4; u++) {
            int c = u * 256 + tid;               // 0..1023
            int row = c >> 3, col = (c & 7) * 8;
            const __nv_bfloat16* g = src + (size_t)(b * TT + r0 + row) * QKVC + coff + col;
            CP_ASYNC16(stile + (row * SLDT + col) * 2, g);
        }
    }
    CP_COMMIT(); CP_WAIT(0);
    __syncthreads();

    uint32_t sQh = sbase, sQl = sbase + STILE_S;
    uint32_t sKh = sbase + 2 * STILE_S, sKl = sbase + 3 * STILE_S;

    float acc[4][4][4];
    #pragma unroll
    for (int i = 0; i < 4; i++)
        #pragma unroll
        for (int j = 0; j < 4; j++)
            #pragma unroll
            for (int e = 0; e < 4; e++) acc[i][j][e] = 0.f;

    #pragma unroll
    for (int ks = 0; ks < 64; ks += 16) {
        uint32_t Ah[4][4], Al[4][4], Bh[4][2], Bl[4][2];
        #pragma unroll
        for (int i = 0; i < 4; i++) {
            uint32_t off = (uint32_t)(((wm * 64 + i * 16 + (lane & 15)) * SLDT
                                       + (lane >> 4) * 8 + ks) * 2);
            LDMX4(Ah[i][0], Ah[i][1], Ah[i][2], Ah[i][3], sQh + off);
            LDMX4(Al[i][0], Al[i][1], Al[i][2], Al[i][3], sQl + off);
        }
        #pragma unroll
        for (int p = 0; p < 2; p++) {
            int sub = lane >> 3;
            uint32_t off = (uint32_t)(((wn * 32 + p * 16 + (lane & 7) + (sub >> 1) * 8) * SLDT
                                       + (sub & 1) * 8 + ks) * 2);
            LDMX4(Bh[2*p][0], Bh[2*p][1], Bh[2*p+1][0], Bh[2*p+1][1], sKh + off);
            LDMX4(Bl[2*p][0], Bl[2*p][1], Bl[2*p+1][0], Bl[2*p+1][1], sKl + off);
        }
        #pragma unroll
        for (int i = 0; i < 4; i++)
            #pragma unroll
            for (int j = 0; j < 4; j++)
                MMA16816(acc[i][j], Ah[i], Bh[j]);
        #pragma unroll
        for (int i = 0; i < 4; i++)
            #pragma unroll
            for (int j = 0; j < 4; j++)
                MMA16816(acc[i][j], Al[i], Bh[j]);
        #pragma unroll
        for (int i = 0; i < 4; i++)
            #pragma unroll
            for (int j = 0; j < 4; j++)
                MMA16816(acc[i][j], Ah[i], Bl[j]);
    }

    float* Pb = P + (size_t)bh * TT * TT;
    #pragma unroll
    for (int i = 0; i < 4; i++) {
        int r = i0 + wm * 64 + i * 16 + (lane >> 2);
        #pragma unroll
        for (int j = 0; j < 4; j++) {
            int cix = j0 + wn * 32 + j * 8 + (lane & 3) * 2;
            *(float2*)(Pb + (size_t)r * TT + cix)
                = make_float2(acc[i][j][0] * 0.125f, acc[i][j][1] * 0.125f);
            *(float2*)(Pb + (size_t)(r + 8) * TT + cix)
                = make_float2(acc[i][j][2] * 0.125f, acc[i][j][3] * 0.125f);
        }
    }
}

// ======================= softmax (fp32 in, bf16 hi/lo out) ==================
__global__ void __launch_bounds__(256)
softmax_kernel(const float* __restrict__ P,
               const __nv_bfloat16* __restrict__ qkvh, const __nv_bfloat16* __restrict__ qkvl,
               const float* __restrict__ rk, const float* __restrict__ mask,
               __nv_bfloat16* __restrict__ phi, __nv_bfloat16* __restrict__ plo)
{
    int row = blockIdx.x;
    int qi  = row % TT;
    int bh  = row / TT;
    int b = bh >> 3, h = bh & 7;
    int tid = threadIdx.x;

    __shared__ float rel9[NWIN];
    __shared__ float red[256];

    if (tid < NWIN) {
        const __nv_bfloat16* qh = qkvh + (size_t)(b*TT + qi) * QKVC + h*KC;
        const __nv_bfloat16* ql = qkvl + (size_t)(b*TT + qi) * QKVC + h*KC;
        const float* rkj = rk + tid * KC;
        float s = 0.f;
        #pragma unroll 8
        for (int d = 0; d < KC; d++)
            s += (__bfloat162float(qh[d]) + __bfloat162float(ql[d])) * rkj[d];
        rel9[tid] = s * 0.125f;
    }
    __syncthreads();

    float mq = mask[b*TT + qi];
    const float* prow = P + (size_t)row * TT;
    float vals[3];
    float mx = -1e30f;
    #pragma unroll
    for (int u = 0; u < 3; u++) {
        int k = tid + u*256;
        float s = prow[k];
        int j = k - qi + 4;
        if ((unsigned)j < (unsigned)NWIN) s += rel9[j];
        if (mq * mask[b*TT + k] == 0.f) s = -10000.f;
        vals[u] = s;
        mx = fmaxf(mx, s);
    }
    red[tid] = mx; __syncthreads();
    for (int s = 128; s > 0; s >>= 1) {
        if (tid < s) red[tid] = fmaxf(red[tid], red[tid+s]);
        __syncthreads();
    }
    mx = red[0]; __syncthreads();

    float sum = 0.f;
    #pragma unroll
    for (int u = 0; u < 3; u++) { vals[u] = expf(vals[u] - mx); sum += vals[u]; }
    red[tid] = sum; __syncthreads();
    for (int s = 128; s > 0; s >>= 1) {
        if (tid < s) red[tid] += red[tid+s];
        __syncthreads();
    }
    float inv = 1.f / red[0];
    #pragma unroll
    for (int u = 0; u < 3; u++) {
        float v = vals[u] * inv;
        __nv_bfloat16 hh, ll; split_bf16(v, hh, ll);
        phi[(size_t)row * TT + tid + u*256] = hh;
        plo[(size_t)row * TT + tid + u*256] = ll;
    }
}

// ======================= P @ V via mma (+ rel_v band) =======================
// O[i, d] = sum_k P[i,k] V[k,d] + band.  M-tile 128, N=64, K=768 (12 stages x 64).
#define PVK     64
#define PV_PB   (128*SLDT*2)        // P tile bytes (hi or lo)
#define PV_VB   (64*SLDT*2)         // V tile bytes
#define PV_STG  (2*PV_PB + 2*PV_VB) // 55296
#define DSMEM_PV (2*PV_STG)         // 110592

__global__ void __launch_bounds__(256, 1)
pv_mma_kernel(const __nv_bfloat16* __restrict__ phi, const __nv_bfloat16* __restrict__ plo,
              const __nv_bfloat16* __restrict__ qkvh, const __nv_bfloat16* __restrict__ qkvl,
              const float* __restrict__ rv,
              __nv_bfloat16* __restrict__ ohi, __nv_bfloat16* __restrict__ olo)
{
    extern __shared__ unsigned char dsm[];
    const int tid  = threadIdx.x;
    const int lane = tid & 31, warp = tid >> 5;
    const int wm = warp >> 2, wn = warp & 3;
    const int bh = blockIdx.y, b = bh >> 3, h = bh & 7;
    const int i0 = blockIdx.x * 128;
    const uint32_t sbase = smem_u32(dsm);

    float acc[4][2][4];
    #pragma unroll
    for (int i = 0; i < 4; i++)
        #pragma unroll
        for (int j = 0; j < 2; j++)
            #pragma unroll
            for (int e = 0; e < 4; e++) acc[i][j][e] = 0.f;

    auto load_stage = [&](int kt, int s) {
        const int k0 = kt * PVK;
        uint32_t sst = sbase + s * PV_STG;
        // P hi/lo: 128 rows x 64 k
        #pragma unroll
        for (int t = 0; t < 2; t++) {
            const __nv_bfloat16* src = t ? plo : phi;
            uint32_t stile = sst + t * PV_PB;
            #pragma unroll
            for (int u = 0; u < 4; u++) {
                int c = u * 256 + tid;
                int row = c >> 3, col = (c & 7) * 8;
                const __nv_bfloat16* g = src + (size_t)(bh * TT + i0 + row) * TT + k0 + col;
                CP_ASYNC16(stile + (row * SLDT + col) * 2, g);
            }
        }
        // V hi/lo: 64 rows (tokens) x 64 d
        #pragma unroll
        for (int t = 0; t < 2; t++) {
            const __nv_bfloat16* src = t ? qkvl : qkvh;
            uint32_t stile = sst + 2 * PV_PB + t * PV_VB;
            #pragma unroll
            for (int u = 0; u < 2; u++) {
                int c = u * 256 + tid;
                int row = c >> 3, col = (c & 7) * 8;
                const __nv_bfloat16* g = src + (size_t)(b * TT + k0 + row) * QKVC
                                         + 2 * CC + h * KC + col;
                CP_ASYNC16(stile + (row * SLDT + col) * 2, g);
            }
        }
    };

    load_stage(0, 0);
    CP_COMMIT();

    const int nk = TT / PVK;   // 12
    int buf = 0;
    for (int kt = 0; kt < nk; kt++) {
        if (kt + 1 < nk) { load_stage(kt + 1, buf ^ 1); CP_COMMIT(); CP_WAIT(1); }
        else             { CP_WAIT(0); }
        __syncthreads();

        uint32_t sPh = sbase + buf * PV_STG;
        uint32_t sPl = sPh + PV_PB;
        uint32_t sVh = sPh + 2 * PV_PB;
        uint32_t sVl = sVh + PV_VB;

        #pragma unroll
        for (int ks = 0; ks < PVK; ks += 16) {
            uint32_t Ah[4][4], Al[4][4], Bh[2][2], Bl[2][2];
            #pragma unroll
            for (int i = 0; i < 4; i++) {
                uint32_t off = (uint32_t)(((wm * 64 + i * 16 + (lane & 15)) * SLDT
                                           + (lane >> 4) * 8 + ks) * 2);
                LDMX4(Ah[i][0], Ah[i][1], Ah[i][2], Ah[i][3], sPh + off);
                LDMX4(Al[i][0], Al[i][1], Al[i][2], Al[i][3], sPl + off);
            }
            {
                int g = lane >> 3;                        // 0..3
                int krow = ks + (g & 1) * 8 + (lane & 7);
                int ncol = wn * 16 + (g >> 1) * 8;
                uint32_t off = (uint32_t)((krow * SLDT + ncol) * 2);
                LDMX4T(Bh[0][0], Bh[0][1], Bh[1][0], Bh[1][1], sVh + off);
                LDMX4T(Bl[0][0], Bl[0][1], Bl[1][0], Bl[1][1], sVl + off);
            }
            #pragma unroll
            for (int i = 0; i < 4; i++)
                #pragma unroll
                for (int j = 0; j < 2; j++)
                    MMA16816(acc[i][j], Ah[i], Bh[j]);
            #pragma unroll
            for (int i = 0; i < 4; i++)
                #pragma unroll
                for (int j = 0; j < 2; j++)
                    MMA16816(acc[i][j], Al[i], Bh[j]);
            #pragma unroll
            for (int i = 0; i < 4; i++)
                #pragma unroll
                for (int j = 0; j < 2; j++)
                    MMA16816(acc[i][j], Ah[i], Bl[j]);
        }
        __syncthreads();
        buf ^= 1;
    }

    // rel_v band: stage p[128][9] and rv[9][64] in smem (reuse dsm)
    float* band = (float*)dsm;                 // 128*9 floats
    float* rvs  = band + 128 * NWIN;           // 9*64 floats
    for (int idx = tid; idx < 128 * NWIN; idx += 256) {
        int r = idx / NWIN, j5 = idx % NWIN;
        int t = i0 + r, k = t + j5 - 4;
        float v = 0.f;
        if ((unsigned)k < (unsigned)TT) {
            size_t o = (size_t)(bh * TT + t) * TT + k;
            v = __bfloat162float(phi[o]) + __bfloat162float(plo[o]);
        }
        band[idx] = v;
    }
    for (int idx = tid; idx < NWIN * KC; idx += 256) rvs[idx] = rv[idx];
    __syncthreads();

    #pragma unroll
    for (int i = 0; i < 4; i++) {
        int rl = wm * 64 + i * 16 + (lane >> 2);   // local row (and +8)
        #pragma unroll
        for (int j = 0; j < 2; j++) {
            int c = wn * 16 + j * 8 + (lane & 3) * 2;
            float v[4] = { acc[i][j][0], acc[i][j][1], acc[i][j][2], acc[i][j][3] };
            #pragma unroll
            for (int j5 = 0; j5 < NWIN; j5++) {
                float p0 = band[rl * NWIN + j5];
                float p1 = band[(rl + 8) * NWIN + j5];
                float r0 = rvs[j5 * KC + c], r1 = rvs[j5 * KC + c + 1];
                v[0] += p0 * r0; v[1] += p0 * r1;
                v[2] += p1 * r0; v[3] += p1 * r1;
            }
            size_t o0 = (size_t)(b * TT + i0 + rl) * CC + h * KC + c;
            size_t o1 = o0 + 8 * CC;
            __nv_bfloat16 h0, l0, h1, l1;
            split_bf16(v[0], h0, l0); split_bf16(v[1], h1, l1);
            *(__nv_bfloat162*)(ohi + o0) = __halves2bfloat162(h0, h1);
            *(__nv_bfloat162*)(olo + o0) = __halves2bfloat162(l0, l1);
            split_bf16(v[2], h0, l0); split_bf16(v[3], h1, l1);
            *(__nv_bfloat162*)(ohi + o1) = __halves2bfloat162(h0, h1);
            *(__nv_bfloat162*)(olo + o1) = __halves2bfloat162(l0, l1);
        }
    }
}

// ---------------- fused residual + LayerNorm (+ bf16 hi/lo out) ------------
__global__ void __launch_bounds__(256)
addln_kernel(const float* __restrict__ X, const float* __restrict__ Y,
             const float* __restrict__ ymask, const float* __restrict__ sc,
             const float* __restrict__ bi, float* __restrict__ Xout,
             __nv_bfloat16* __restrict__ ohi, __nv_bfloat16* __restrict__ olo,
             const float* __restrict__ hmask)
{
    int row = blockIdx.x;
    int tid = threadIdx.x;
    float m = ymask ? ymask[row] : 1.0f;
    const float* xr = X + (size_t)row * CC;
    const float* yr = Y + (size_t)row * CC;
    float v0 = xr[tid]       + yr[tid]       * m;
    float v1 = xr[tid + 256] + yr[tid + 256] * m;

    __shared__ float red[256];
    red[tid] = v0 + v1; __syncthreads();
    for (int s = 128; s > 0; s >>= 1) {
        if (tid < s) red[tid] += red[tid+s];
        __syncthreads();
    }
    float mean = red[0] * (1.0f / CC);
    __syncthreads();
    float d0 = v0 - mean, d1 = v1 - mean;
    red[tid] = d0*d0 + d1*d1; __syncthreads();
    for (int s = 128; s > 0; s >>= 1) {
        if (tid < s) red[tid] += red[tid+s];
        __syncthreads();
    }
    float r = rsqrtf(red[0] * (1.0f / CC) + 1e-6f);
    float o0 = d0 * r * sc[tid]       + bi[tid];
    float o1 = d1 * r * sc[tid + 256] + bi[tid + 256];
    Xout[(size_t)row*CC + tid]       = o0;
    Xout[(size_t)row*CC + tid + 256] = o1;
    if (ohi) {
        float hm = hmask ? hmask[row] : 1.0f;
        __nv_bfloat16 hh, ll;
        split_bf16(o0 * hm, hh, ll);
        ohi[(size_t)row*CC + tid] = hh;  olo[(size_t)row*CC + tid] = ll;
        split_bf16(o1 * hm, hh, ll);
        ohi[(size_t)row*CC + tid + 256] = hh;  olo[(size_t)row*CC + tid + 256] = ll;
    }
}

// ---------------- host orchestration ---------------------------------------
extern "C" void kernel_launch(void* const* d_in, const int* in_sizes, int n_in,
                              void* d_out, int out_size)
{
    const float* x    = (const float*)d_in[0];
    const float* mask = (const float*)d_in[1];
    const float* Wq   = (const float*)d_in[2];
    const float* bq   = (const float*)d_in[3];
    const float* Wk   = (const float*)d_in[4];
    const float* bk   = (const float*)d_in[5];
    const float* Wv   = (const float*)d_in[6];
    const float* bv   = (const float*)d_in[7];
    const float* Wo   = (const float*)d_in[8];
    const float* bo   = (const float*)d_in[9];
    const float* erk  = (const float*)d_in[10];
    const float* erv  = (const float*)d_in[11];
    const float* ln1s = (const float*)d_in[12];
    const float* ln1b = (const float*)d_in[13];
    const float* W1   = (const float*)d_in[14];
    const float* b1   = (const float*)d_in[15];
    const float* W2   = (const float*)d_in[16];
    const float* b2   = (const float*)d_in[17];
    const float* ln2s = (const float*)d_in[18];
    const float* ln2b = (const float*)d_in[19];
    float* out = (float*)d_out;

    float *px, *py, *pp, *pbias;
    __nv_bfloat16 *xhi, *xlo, *qkvh, *qkvl, *phi, *plo, *paoh, *paol, *h1h, *h1l, *whi, *wlo;
    cudaGetSymbolAddress((void**)&px,   g_x);
    cudaGetSymbolAddress((void**)&py,   g_y);
    cudaGetSymbolAddress((void**)&pp,   g_p);
    cudaGetSymbolAddress((void**)&pbias,g_bias);
    cudaGetSymbolAddress((void**)&xhi,  g_xhi);
    cudaGetSymbolAddress((void**)&xlo,  g_xlo);
    cudaGetSymbolAddress((void**)&qkvh, g_qkvhi);
    cudaGetSymbolAddress((void**)&qkvl, g_qkvlo);
    cudaGetSymbolAddress((void**)&phi,  g_phi);
    cudaGetSymbolAddress((void**)&plo,  g_plo);
    cudaGetSymbolAddress((void**)&paoh, g_paohi);
    cudaGetSymbolAddress((void**)&paol, g_paolo);
    cudaGetSymbolAddress((void**)&h1h,  g_h1hi);
    cudaGetSymbolAddress((void**)&h1l,  g_h1lo);
    cudaGetSymbolAddress((void**)&whi,  g_whi);
    cudaGetSymbolAddress((void**)&wlo,  g_wlo);

    cudaFuncSetAttribute(mma_gemm_kernel,  cudaFuncAttributeMaxDynamicSharedMemorySize, DSMEM_G);
    cudaFuncSetAttribute(scores_mma_kernel,cudaFuncAttributeMaxDynamicSharedMemorySize, DSMEM_S);
    cudaFuncSetAttribute(pv_mma_kernel,    cudaFuncAttributeMaxDynamicSharedMemorySize, DSMEM_PV);

    const int NE = BT * CC;
    init_kernel<<<(NE + 255)/256, 256>>>(x, mask, px, xhi, xlo);

    dim3 gQKV(QKVC/128, BT/128);   // 12 x 48
    dim3 gWoP(CC/128, BT/128);     // 4 x 48
    dim3 gFF1(FF/128, BT/128);     // 16 x 48
    dim3 gWc(CC/32, CC/32);
    dim3 gW1(FF/32, CC/32);
    dim3 gW2(CC/32, FF/32);
    dim3 blkW(32, 8);
    dim3 gScr(TT/128, TT/128, BB*HH);   // 6 x 6 x 64
    dim3 gPV (TT/128, BB*HH);           // 6 x 64

    for (int l = 0; l < LL; l++) {
        const float* Wql = Wq + (size_t)l*CC*CC;
        const float* Wkl = Wk + (size_t)l*CC*CC;
        const float* Wvl = Wv + (size_t)l*CC*CC;
        const float* Wol = Wo + (size_t)l*CC*CC;  const float* bol = bo + (size_t)l*CC;
        const float* W1l = W1 + (size_t)l*CC*FF;  const float* b1l = b1 + (size_t)l*FF;
        const float* W2l = W2 + (size_t)l*FF*CC;  const float* b2l = b2 + (size_t)l*CC;
        const float* rkl = erk + (size_t)l*NWIN*KC;
        const float* rvl = erv + (size_t)l*NWIN*KC;

        // --- fused QKV projection (bf16 hi/lo out) ---
        packbias_kernel<<<(QKVC + 255)/256, 256>>>(bq + (size_t)l*CC, bk + (size_t)l*CC,
                                                   bv + (size_t)l*CC, pbias);
        convertWt_kernel<<<gWc, blkW>>>(Wql, whi,              wlo,              CC, CC);
        convertWt_kernel<<<gWc, blkW>>>(Wkl, whi + (size_t)CC*CC,   wlo + (size_t)CC*CC,   CC, CC);
        convertWt_kernel<<<gWc, blkW>>>(Wvl, whi + (size_t)2*CC*CC, wlo + (size_t)2*CC*CC, CC, CC);
        mma_gemm_kernel<<<gQKV, 256, DSMEM_G>>>(xhi, xlo, whi, wlo, pbias,
                                                nullptr, qkvh, qkvl, nullptr, BT, QKVC, CC, 0);

        // --- attention ---
        scores_mma_kernel<<<gScr, 256, DSMEM_S>>>(qkvh, qkvl, pp);
        softmax_kernel<<<BB*HH*TT, 256>>>(pp, qkvh, qkvl, rkl, mask, phi, plo);
        pv_mma_kernel<<<gPV, 256, DSMEM_PV>>>(phi, plo, qkvh, qkvl, rvl, paoh, paol);

        // --- output projection + LN1 (hi/lo masked for FFN1) ---
        convertWt_kernel<<<gWc, blkW>>>(Wol, whi, wlo, CC, CC);
        mma_gemm_kernel<<<gWoP, 256, DSMEM_G>>>(paoh, paol, whi, wlo, bol,
                                                py, nullptr, nullptr, nullptr, BT, CC, CC, 0);
        addln_kernel<<<BT, 256>>>(px, py, nullptr, ln1s + (size_t)l*CC, ln1b + (size_t)l*CC,
                                  px, xhi, xlo, mask);

        // --- FFN ---
        convertWt_kernel<<<gW1, blkW>>>(W1l, whi, wlo, CC, FF);
        mma_gemm_kernel<<<gFF1, 256, DSMEM_G>>>(xhi, xlo, whi, wlo, b1l,
                                                nullptr, h1h, h1l, mask, BT, FF, CC, 1);
        convertWt_kernel<<<gW2, blkW>>>(W2l, whi, wlo, FF, CC);
        mma_gemm_kernel<<<gWoP, 256, DSMEM_G>>>(h1h, h1l, whi, wlo, b2l,
                                                py, nullptr, nullptr, nullptr, BT, CC, FF, 0);
        addln_kernel<<<BT, 256>>>(px, py, mask, ln2s + (size_t)l*CC, ln2b + (size_t)l*CC,
                                  px, xhi, xlo, nullptr);
    }

    maskmul_kernel<<<(NE + 255)/256, 256>>>(px, mask, out, NE);
}

// round 5
// speedup vs baseline: 2.7155x; 1.2647x over previous
#include <cuda_runtime.h>
#include <cuda_bf16.h>
#include <cstdint>
#include <cstddef>

#define BB   8
#define TT   768
#define CC   512
#define FF   2048
#define HH   8
#define KC   64
#define LL   6
#define BT   (BB*TT)      // 6144
#define QKVC (3*CC)       // 1536
#define NWIN 9

// ---------------- scratch (device globals: allocation-free) ----------------
__device__ float g_x [BT*CC];
__device__ float g_y [BT*CC];
__device__ float g_bias[QKVC];
__device__ __nv_bfloat16 g_xhi [BT*CC];
__device__ __nv_bfloat16 g_xlo [BT*CC];
__device__ __nv_bfloat16 g_qkvhi[(size_t)BT*QKVC];
__device__ __nv_bfloat16 g_qkvlo[(size_t)BT*QKVC];
__device__ __nv_bfloat16 g_paohi[BT*CC];
__device__ __nv_bfloat16 g_paolo[BT*CC];
__device__ __nv_bfloat16 g_h1hi[(size_t)BT*FF];
__device__ __nv_bfloat16 g_h1lo[(size_t)BT*FF];
__device__ __nv_bfloat16 g_whi[(size_t)FF*CC];
__device__ __nv_bfloat16 g_wlo[(size_t)FF*CC];

// ======================= baseline-PTX helpers ===============================
static __device__ __forceinline__ uint32_t smem_u32(const void* p) {
    uint32_t a;
    asm("{ .reg .u64 t; cvta.to.shared.u64 t, %1; cvt.u32.u64 %0, t; }" : "=r"(a) : "l"(p));
    return a;
}
#define CP_ASYNC16(saddr, gptr) \
    asm volatile("cp.async.ca.shared.global [%0], [%1], 16;" :: "r"(saddr), "l"(gptr))
#define CP_COMMIT() asm volatile("cp.async.commit_group;")
#define CP_WAIT(n)  asm volatile("cp.async.wait_group %0;" :: "n"(n))

#define LDMX4(r0, r1, r2, r3, addr) \
    asm volatile("ldmatrix.sync.aligned.m8n8.x4.shared.b16 {%0,%1,%2,%3}, [%4];" \
                 : "=r"(r0), "=r"(r1), "=r"(r2), "=r"(r3) : "r"(addr))
#define LDMX4T(r0, r1, r2, r3, addr) \
    asm volatile("ldmatrix.sync.aligned.m8n8.x4.trans.shared.b16 {%0,%1,%2,%3}, [%4];" \
                 : "=r"(r0), "=r"(r1), "=r"(r2), "=r"(r3) : "r"(addr))

#define MMA16816(d, a, b) \
    asm volatile("mma.sync.aligned.m16n8k16.row.col.f32.bf16.bf16.f32 " \
                 "{%0,%1,%2,%3}, {%4,%5,%6,%7}, {%8,%9}, {%0,%1,%2,%3};" \
                 : "+f"((d)[0]), "+f"((d)[1]), "+f"((d)[2]), "+f"((d)[3]) \
                 : "r"((a)[0]), "r"((a)[1]), "r"((a)[2]), "r"((a)[3]), \
                   "r"((b)[0]), "r"((b)[1]))

static __device__ __forceinline__ void split_bf16(float v, __nv_bfloat16& h, __nv_bfloat16& l) {
    h = __float2bfloat16(v);
    l = __float2bfloat16(v - __bfloat162float(h));
}
static __device__ __forceinline__ uint32_t pack_hi2(float a, float b) {
    __nv_bfloat162 p = __halves2bfloat162(__float2bfloat16(a), __float2bfloat16(b));
    return *(uint32_t*)&p;
}
static __device__ __forceinline__ uint32_t pack_lo2(float a, float b) {
    __nv_bfloat16 ha = __float2bfloat16(a), hb = __float2bfloat16(b);
    __nv_bfloat162 p = __halves2bfloat162(__float2bfloat16(a - __bfloat162float(ha)),
                                          __float2bfloat16(b - __bfloat162float(hb)));
    return *(uint32_t*)&p;
}

// ======================= small utility kernels ==============================
__global__ void init_kernel(const float* __restrict__ X, const float* __restrict__ mask,
                            float* __restrict__ Xo,
                            __nv_bfloat16* __restrict__ hi, __nv_bfloat16* __restrict__ lo)
{
    int i = blockIdx.x * 256 + threadIdx.x;
    if (i >= BT*CC) return;
    float v = X[i] * mask[i / CC];
    Xo[i] = v;
    __nv_bfloat16 h, l; split_bf16(v, h, l);
    hi[i] = h; lo[i] = l;
}

__global__ void maskmul_kernel(const float* __restrict__ in, const float* __restrict__ mask,
                               float* __restrict__ out, int n)
{
    int i = blockIdx.x * 256 + threadIdx.x;
    if (i < n) out[i] = in[i] * mask[i / CC];
}

__global__ void packbias_kernel(const float* __restrict__ bq, const float* __restrict__ bk,
                                const float* __restrict__ bv, float* __restrict__ dst)
{
    int i = blockIdx.x * 256 + threadIdx.x;
    if (i >= QKVC) return;
    dst[i] = (i < CC) ? bq[i] : (i < 2*CC) ? bk[i - CC] : bv[i - 2*CC];
}

// W [K,N] fp32 -> Wt [N,K] bf16 hi/lo (transpose + split)
__global__ void convertWt_kernel(const float* __restrict__ W,
                                 __nv_bfloat16* __restrict__ hi, __nv_bfloat16* __restrict__ lo,
                                 int K, int N)
{
    __shared__ float t[32][33];
    int n0 = blockIdx.x * 32, k0 = blockIdx.y * 32;
    int tx = threadIdx.x, ty = threadIdx.y;   // 32 x 8
    #pragma unroll
    for (int r = 0; r < 32; r += 8)
        t[ty + r][tx] = W[(size_t)(k0 + ty + r) * N + n0 + tx];
    __syncthreads();
    #pragma unroll
    for (int r = 0; r < 32; r += 8) {
        float v = t[tx][ty + r];
        __nv_bfloat16 h, l; split_bf16(v, h, l);
        size_t o = (size_t)(n0 + ty + r) * K + k0 + tx;
        hi[o] = h; lo[o] = l;
    }
}

// ======================= dense tensor-core GEMM =============================
#define TILEB   (128*80)
#define STAGEB  (4*TILEB)
#define DSMEM_G (2*STAGEB)

__global__ void __launch_bounds__(256, 1)
mma_gemm_kernel(const __nv_bfloat16* __restrict__ aHi, const __nv_bfloat16* __restrict__ aLo,
                const __nv_bfloat16* __restrict__ bHi, const __nv_bfloat16* __restrict__ bLo,
                const float* __restrict__ bias, float* __restrict__ C,
                __nv_bfloat16* __restrict__ Chi, __nv_bfloat16* __restrict__ Clo,
                const float* __restrict__ rowmask,
                int M, int N, int K, int relu)
{
    extern __shared__ unsigned char dsm[];
    const int tid  = threadIdx.x;
    const int lane = tid & 31, warp = tid >> 5;
    const int wm = warp >> 2, wn = warp & 3;
    const int bm = blockIdx.y * 128;
    const int bn = blockIdx.x * 128;
    const uint32_t sbase = smem_u32(dsm);

    float acc[4][4][4];
    #pragma unroll
    for (int i = 0; i < 4; i++)
        #pragma unroll
        for (int j = 0; j < 4; j++)
            #pragma unroll
            for (int e = 0; e < 4; e++) acc[i][j][e] = 0.f;

    const int nk = K >> 5;

    auto load_stage = [&](int kt, int s) {
        const int kt0 = kt << 5;
        uint32_t sst = sbase + s * STAGEB;
        #pragma unroll
        for (int t = 0; t < 4; t++) {
            const __nv_bfloat16* src = (t == 0) ? aHi : (t == 1) ? aLo : (t == 2) ? bHi : bLo;
            const int r0 = (t < 2) ? bm : bn;
            uint32_t stile = sst + t * TILEB;
            #pragma unroll
            for (int u = 0; u < 2; u++) {
                int c = u * 256 + tid;
                int row = c >> 2, col = (c & 3) * 8;
                const __nv_bfloat16* g = src + (size_t)(r0 + row) * K + kt0 + col;
                CP_ASYNC16(stile + row * 80 + col * 2, g);
            }
        }
    };

    load_stage(0, 0);
    CP_COMMIT();

    int buf = 0;
    for (int kt = 0; kt < nk; kt++) {
        if (kt + 1 < nk) { load_stage(kt + 1, buf ^ 1); CP_COMMIT(); CP_WAIT(1); }
        else             { CP_WAIT(0); }
        __syncthreads();

        uint32_t sAh = sbase + buf * STAGEB;
        uint32_t sAl = sAh + TILEB;
        uint32_t sBh = sAh + 2 * TILEB;
        uint32_t sBl = sAh + 3 * TILEB;

        #pragma unroll
        for (int ks = 0; ks < 32; ks += 16) {
            uint32_t Ah[4][4], Al[4][4], Bh[4][2], Bl[4][2];
            #pragma unroll
            for (int i = 0; i < 4; i++) {
                uint32_t off = (uint32_t)((wm * 64 + i * 16 + (lane & 15)) * 80
                                          + ((lane >> 4) * 8 + ks) * 2);
                LDMX4(Ah[i][0], Ah[i][1], Ah[i][2], Ah[i][3], sAh + off);
                LDMX4(Al[i][0], Al[i][1], Al[i][2], Al[i][3], sAl + off);
            }
            #pragma unroll
            for (int p = 0; p < 2; p++) {
                int sub = lane >> 3;
                uint32_t off = (uint32_t)((wn * 32 + p * 16 + (lane & 7) + (sub >> 1) * 8) * 80
                                          + ((sub & 1) * 8 + ks) * 2);
                LDMX4(Bh[2*p][0], Bh[2*p][1], Bh[2*p+1][0], Bh[2*p+1][1], sBh + off);
                LDMX4(Bl[2*p][0], Bl[2*p][1], Bl[2*p+1][0], Bl[2*p+1][1], sBl + off);
            }
            #pragma unroll
            for (int i = 0; i < 4; i++)
                #pragma unroll
                for (int j = 0; j < 4; j++)
                    MMA16816(acc[i][j], Ah[i], Bh[j]);
            #pragma unroll
            for (int i = 0; i < 4; i++)
                #pragma unroll
                for (int j = 0; j < 4; j++)
                    MMA16816(acc[i][j], Al[i], Bh[j]);
            #pragma unroll
            for (int i = 0; i < 4; i++)
                #pragma unroll
                for (int j = 0; j < 4; j++)
                    MMA16816(acc[i][j], Ah[i], Bl[j]);
        }
        __syncthreads();
        buf ^= 1;
    }

    #pragma unroll
    for (int i = 0; i < 4; i++) {
        int r = bm + wm * 64 + i * 16 + (lane >> 2);
        float m0 = rowmask ? rowmask[r]     : 1.f;
        float m1 = rowmask ? rowmask[r + 8] : 1.f;
        #pragma unroll
        for (int j = 0; j < 4; j++) {
            int cix = bn + wn * 32 + j * 8 + (lane & 3) * 2;
            float b0 = bias[cix], b1 = bias[cix + 1];
            float v[4];
            v[0] = acc[i][j][0] + b0; v[1] = acc[i][j][1] + b1;
            v[2] = acc[i][j][2] + b0; v[3] = acc[i][j][3] + b1;
            if (relu) {
                #pragma unroll
                for (int e = 0; e < 4; e++) v[e] = fmaxf(v[e], 0.f);
            }
            v[0] *= m0; v[1] *= m0; v[2] *= m1; v[3] *= m1;
            if (C) {
                *(float2*)(C + (size_t)r * N + cix)       = make_float2(v[0], v[1]);
                *(float2*)(C + (size_t)(r + 8) * N + cix) = make_float2(v[2], v[3]);
            }
            if (Chi) {
                *(__nv_bfloat162*)(Chi + (size_t)r * N + cix)       = *(__nv_bfloat162*)&(uint32_t&)*(uint32_t[]){pack_hi2(v[0], v[1])};
                *(__nv_bfloat162*)(Clo + (size_t)r * N + cix)       = *(__nv_bfloat162*)&(uint32_t&)*(uint32_t[]){pack_lo2(v[0], v[1])};
                *(__nv_bfloat162*)(Chi + (size_t)(r + 8) * N + cix) = *(__nv_bfloat162*)&(uint32_t&)*(uint32_t[]){pack_hi2(v[2], v[3])};
                *(__nv_bfloat162*)(Clo + (size_t)(r + 8) * N + cix) = *(__nv_bfloat162*)&(uint32_t&)*(uint32_t[]){pack_lo2(v[2], v[3])};
            }
        }
    }
}

// ======================= fused flash attention ==============================
// Per (bh, 128-row Q tile): S = 0.125*Q K^T + rel_k band, mask, online softmax,
// O = P V (+ rel_v band). Everything split-bf16 3-product, fp32 accum.
#define FLDT 72
#define FT_B (128*FLDT*2)     // 18432 B
// smem map (bytes):
//   Qh @0, Ql @FT_B
//   stage s in {0,1}: Kh,Kl,Vh,Vl @ 2*FT_B + s*4*FT_B
//   band @ 10*FT_B               : 128*12 f32
//   rel9 @ +6144                 : 128*12 f32
//   rvs  @ +6144                 : 9*64 f32
//   maskS@ +2304                 : 768 f32
#define DSMEM_F (10*FT_B + 6144 + 6144 + 2304 + 3072)

__global__ void __launch_bounds__(256, 1)
flash_kernel(const __nv_bfloat16* __restrict__ qkvh, const __nv_bfloat16* __restrict__ qkvl,
             const float* __restrict__ rk, const float* __restrict__ rv,
             const float* __restrict__ mask,
             __nv_bfloat16* __restrict__ ohi, __nv_bfloat16* __restrict__ olo)
{
    extern __shared__ unsigned char dsm[];
    const int tid  = threadIdx.x;
    const int lane = tid & 31, warp = tid >> 5;
    const int gq = lane >> 2, qt = lane & 3;
    const int bh = blockIdx.y, b = bh >> 3, h = bh & 7;
    const int i0 = blockIdx.x * 128;
    const uint32_t sbase = smem_u32(dsm);
    const uint32_t sQh = sbase, sQl = sbase + FT_B;

    float* band  = (float*)(dsm + 10*FT_B);
    float* rel9  = band + 128*12;
    float* rvs   = rel9 + 128*12;
    float* maskS = rvs + 9*64;
    const uint32_t uband  = smem_u32(band);   (void)uband;

    // --- async loads: Q tile (group 0), K/V tile 0 (group 1) ---
    #pragma unroll
    for (int t = 0; t < 2; t++) {
        const __nv_bfloat16* src = t ? qkvl : qkvh;
        uint32_t tile = sQh + t * FT_B;
        #pragma unroll
        for (int u = 0; u < 4; u++) {
            int c = u * 256 + tid;
            int row = c >> 3, col = (c & 7) * 8;
            const __nv_bfloat16* g = src + (size_t)(b*TT + i0 + row) * QKVC + h*KC + col;
            CP_ASYNC16(tile + (row * FLDT + col) * 2, g);
        }
    }
    CP_COMMIT();

    auto load_kv = [&](int jt, int s) {
        int j0 = jt * 128;
        uint32_t sst = sbase + 2*FT_B + s * 4*FT_B;
        #pragma unroll
        for (int t = 0; t < 4; t++) {
            const __nv_bfloat16* src = (t & 1) ? qkvl : qkvh;
            const int coff = (t < 2) ? CC + h*KC : 2*CC + h*KC;
            uint32_t tile = sst + t * FT_B;
            #pragma unroll
            for (int u = 0; u < 4; u++) {
                int c = u * 256 + tid;
                int row = c >> 3, col = (c & 7) * 8;
                const __nv_bfloat16* g = src + (size_t)(b*TT + j0 + row) * QKVC + coff + col;
                CP_ASYNC16(tile + (row * FLDT + col) * 2, g);
            }
        }
    };
    load_kv(0, 0);
    CP_COMMIT();

    // --- plain smem init while TMA-ish loads fly ---
    for (int idx = tid; idx < TT; idx += 256) maskS[idx] = mask[b*TT + idx];
    for (int idx = tid; idx < NWIN*KC; idx += 256) rvs[idx] = rv[idx];
    for (int idx = tid; idx < 128*NWIN; idx += 256)
        band[(idx/NWIN)*12 + (idx%NWIN)] = -1e30f;

    CP_WAIT(1);          // Q ready
    __syncthreads();

    // rel9[r][j5] = 0.125 * <q_r, rk_j5>
    for (int idx = tid; idx < 128*NWIN; idx += 256) {
        int r = idx / NWIN, j5 = idx % NWIN;
        const float* rkj = rk + j5 * KC;
        float s = 0.f;
        #pragma unroll 8
        for (int d = 0; d < KC; d++) {
            float qv = __bfloat162float(*(__nv_bfloat16*)(dsm + (r*FLDT + d)*2))
                     + __bfloat162float(*(__nv_bfloat16*)(dsm + FT_B + (r*FLDT + d)*2));
            s += qv * rkj[d];
        }
        rel9[r*12 + j5] = s * 0.125f;
    }
    __syncthreads();

    const int lr0 = warp*16 + gq, lr1 = lr0 + 8;
    const float mq0 = maskS[i0 + lr0], mq1 = maskS[i0 + lr1];

    float m0 = -1e30f, m1 = -1e30f, l0 = 0.f, l1 = 0.f;
    float O[8][4];
    #pragma unroll
    for (int nb = 0; nb < 8; nb++)
        #pragma unroll
        for (int e = 0; e < 4; e++) O[nb][e] = 0.f;

    for (int jt = 0; jt < 6; jt++) {
        if (jt + 1 < 6) { load_kv(jt + 1, (jt + 1) & 1); CP_COMMIT(); CP_WAIT(1); }
        else            { CP_WAIT(0); }
        __syncthreads();

        uint32_t sst = sbase + 2*FT_B + (jt & 1) * 4*FT_B;
        uint32_t sKh = sst, sKl = sst + FT_B, sVh = sst + 2*FT_B, sVl = sst + 3*FT_B;
        const int j0 = jt * 128;

        // ---- S = (Qh+Ql)(Kh+Kl)^T, 3 products ----
        float sacc[16][4];
        #pragma unroll
        for (int nb = 0; nb < 16; nb++)
            #pragma unroll
            for (int e = 0; e < 4; e++) sacc[nb][e] = 0.f;

        #pragma unroll
        for (int ks = 0; ks < 64; ks += 16) {
            uint32_t Ah[4], Al[4];
            uint32_t aoff = (uint32_t)(((warp*16 + (lane & 15)) * FLDT + (lane >> 4) * 8 + ks) * 2);
            LDMX4(Ah[0], Ah[1], Ah[2], Ah[3], sQh + aoff);
            LDMX4(Al[0], Al[1], Al[2], Al[3], sQl + aoff);
            #pragma unroll
            for (int p = 0; p < 8; p++) {
                int sub = lane >> 3;
                uint32_t boff = (uint32_t)(((p*16 + (lane & 7) + (sub >> 1) * 8) * FLDT
                                            + (sub & 1) * 8 + ks) * 2);
                uint32_t Bh[2][2], Bl[2][2];
                LDMX4(Bh[0][0], Bh[0][1], Bh[1][0], Bh[1][1], sKh + boff);
                LDMX4(Bl[0][0], Bl[0][1], Bl[1][0], Bl[1][1], sKl + boff);
                MMA16816(sacc[2*p],   Ah, Bh[0]); MMA16816(sacc[2*p+1], Ah, Bh[1]);
                MMA16816(sacc[2*p],   Al, Bh[0]); MMA16816(sacc[2*p+1], Al, Bh[1]);
                MMA16816(sacc[2*p],   Ah, Bl[0]); MMA16816(sacc[2*p+1], Ah, Bl[1]);
            }
        }

        // ---- scale + rel band + mask + band capture ----
        #pragma unroll
        for (int nb = 0; nb < 16; nb++) {
            int colb = j0 + nb*8 + qt*2;
            #pragma unroll
            for (int e = 0; e < 4; e++) {
                int row = (e < 2) ? (i0 + lr0) : (i0 + lr1);
                int lr  = (e < 2) ? lr0 : lr1;
                float mq = (e < 2) ? mq0 : mq1;
                int col = colb + (e & 1);
                float v = sacc[nb][e] * 0.125f;
                int d = col - row + 4;
                if ((unsigned)d < (unsigned)NWIN) v += rel9[lr*12 + d];
                if (mq * maskS[col] == 0.f) v = -10000.f;
                if ((unsigned)d < (unsigned)NWIN) band[lr*12 + d] = v;
                sacc[nb][e] = v;
            }
        }

        // ---- online softmax: quad-local row reduce ----
        float mx0 = -1e30f, mx1 = -1e30f;
        #pragma unroll
        for (int nb = 0; nb < 16; nb++) {
            mx0 = fmaxf(mx0, fmaxf(sacc[nb][0], sacc[nb][1]));
            mx1 = fmaxf(mx1, fmaxf(sacc[nb][2], sacc[nb][3]));
        }
        mx0 = fmaxf(mx0, __shfl_xor_sync(0xffffffffu, mx0, 1));
        mx0 = fmaxf(mx0, __shfl_xor_sync(0xffffffffu, mx0, 2));
        mx1 = fmaxf(mx1, __shfl_xor_sync(0xffffffffu, mx1, 1));
        mx1 = fmaxf(mx1, __shfl_xor_sync(0xffffffffu, mx1, 2));
        float mn0 = fmaxf(m0, mx0), mn1 = fmaxf(m1, mx1);
        float f0 = __expf(m0 - mn0), f1 = __expf(m1 - mn1);
        float s0 = 0.f, s1 = 0.f;
        #pragma unroll
        for (int nb = 0; nb < 16; nb++) {
            sacc[nb][0] = __expf(sacc[nb][0] - mn0);
            sacc[nb][1] = __expf(sacc[nb][1] - mn0);
            sacc[nb][2] = __expf(sacc[nb][2] - mn1);
            sacc[nb][3] = __expf(sacc[nb][3] - mn1);
            s0 += sacc[nb][0] + sacc[nb][1];
            s1 += sacc[nb][2] + sacc[nb][3];
        }
        s0 += __shfl_xor_sync(0xffffffffu, s0, 1);
        s0 += __shfl_xor_sync(0xffffffffu, s0, 2);
        s1 += __shfl_xor_sync(0xffffffffu, s1, 1);
        s1 += __shfl_xor_sync(0xffffffffu, s1, 2);
        l0 = l0 * f0 + s0;  l1 = l1 * f1 + s1;
        m0 = mn0;  m1 = mn1;
        #pragma unroll
        for (int nb = 0; nb < 8; nb++) {
            O[nb][0] *= f0; O[nb][1] *= f0; O[nb][2] *= f1; O[nb][3] *= f1;
        }

        // ---- O += P~ V  (P from registers, split hi/lo; V hi/lo from smem) ----
        #pragma unroll
        for (int kb = 0; kb < 8; kb++) {
            uint32_t Ph[4], Pl[4];
            Ph[0] = pack_hi2(sacc[2*kb][0],   sacc[2*kb][1]);
            Ph[1] = pack_hi2(sacc[2*kb][2],   sacc[2*kb][3]);
            Ph[2] = pack_hi2(sacc[2*kb+1][0], sacc[2*kb+1][1]);
            Ph[3] = pack_hi2(sacc[2*kb+1][2], sacc[2*kb+1][3]);
            Pl[0] = pack_lo2(sacc[2*kb][0],   sacc[2*kb][1]);
            Pl[1] = pack_lo2(sacc[2*kb][2],   sacc[2*kb][3]);
            Pl[2] = pack_lo2(sacc[2*kb+1][0], sacc[2*kb+1][1]);
            Pl[3] = pack_lo2(sacc[2*kb+1][2], sacc[2*kb+1][3]);
            #pragma unroll
            for (int vb = 0; vb < 4; vb++) {
                int g = lane >> 3;
                int krow = kb*16 + (g & 1) * 8 + (lane & 7);
                int ncol = vb*16 + (g >> 1) * 8;
                uint32_t off = (uint32_t)((krow * FLDT + ncol) * 2);
                uint32_t Vh[2][2], Vl[2][2];
                LDMX4T(Vh[0][0], Vh[0][1], Vh[1][0], Vh[1][1], sVh + off);
                LDMX4T(Vl[0][0], Vl[0][1], Vl[1][0], Vl[1][1], sVl + off);
                MMA16816(O[2*vb],   Ph, Vh[0]); MMA16816(O[2*vb+1], Ph, Vh[1]);
                MMA16816(O[2*vb],   Pl, Vh[0]); MMA16816(O[2*vb+1], Pl, Vh[1]);
                MMA16816(O[2*vb],   Ph, Vl[0]); MMA16816(O[2*vb+1], Ph, Vl[1]);
            }
        }
        __syncthreads();
    }

    // ---- epilogue: normalize, rel_v band, write bf16 hi/lo ----
    float inv0 = 1.f / l0, inv1 = 1.f / l1;
    float bp0[NWIN], bp1[NWIN];
    #pragma unroll
    for (int j5 = 0; j5 < NWIN; j5++) {
        bp0[j5] = __expf(band[lr0*12 + j5] - m0) * inv0;
        bp1[j5] = __expf(band[lr1*12 + j5] - m1) * inv1;
    }
    #pragma unroll
    for (int nb = 0; nb < 8; nb++) {
        int c = nb*8 + qt*2;
        float v0 = O[nb][0] * inv0, v1 = O[nb][1] * inv0;
        float v2 = O[nb][2] * inv1, v3 = O[nb][3] * inv1;
        #pragma unroll
        for (int j5 = 0; j5 < NWIN; j5++) {
            float r0 = rvs[j5*KC + c], r1 = rvs[j5*KC + c + 1];
            v0 += bp0[j5]*r0; v1 += bp0[j5]*r1;
            v2 += bp1[j5]*r0; v3 += bp1[j5]*r1;
        }
        size_t o0 = (size_t)(b*TT + i0 + lr0) * CC + h*KC + c;
        size_t o1 = (size_t)(b*TT + i0 + lr1) * CC + h*KC + c;
        uint32_t ph, pl;
        ph = pack_hi2(v0, v1); pl = pack_lo2(v0, v1);
        *(uint32_t*)(ohi + o0) = ph; *(uint32_t*)(olo + o0) = pl;
        ph = pack_hi2(v2, v3); pl = pack_lo2(v2, v3);
        *(uint32_t*)(ohi + o1) = ph; *(uint32_t*)(olo + o1) = pl;
    }
}

// ---------------- fused residual + LayerNorm (+ bf16 hi/lo out) ------------
__global__ void __launch_bounds__(256)
addln_kernel(const float* __restrict__ X, const float* __restrict__ Y,
             const float* __restrict__ ymask, const float* __restrict__ sc,
             const float* __restrict__ bi, float* __restrict__ Xout,
             __nv_bfloat16* __restrict__ ohi, __nv_bfloat16* __restrict__ olo,
             const float* __restrict__ hmask)
{
    int row = blockIdx.x;
    int tid = threadIdx.x;
    float m = ymask ? ymask[row] : 1.0f;
    const float* xr = X + (size_t)row * CC;
    const float* yr = Y + (size_t)row * CC;
    float v0 = xr[tid]       + yr[tid]       * m;
    float v1 = xr[tid + 256] + yr[tid + 256] * m;

    __shared__ float red[256];
    red[tid] = v0 + v1; __syncthreads();
    for (int s = 128; s > 0; s >>= 1) {
        if (tid < s) red[tid] += red[tid+s];
        __syncthreads();
    }
    float mean = red[0] * (1.0f / CC);
    __syncthreads();
    float d0 = v0 - mean, d1 = v1 - mean;
    red[tid] = d0*d0 + d1*d1; __syncthreads();
    for (int s = 128; s > 0; s >>= 1) {
        if (tid < s) red[tid] += red[tid+s];
        __syncthreads();
    }
    float r = rsqrtf(red[0] * (1.0f / CC) + 1e-6f);
    float o0 = d0 * r * sc[tid]       + bi[tid];
    float o1 = d1 * r * sc[tid + 256] + bi[tid + 256];
    Xout[(size_t)row*CC + tid]       = o0;
    Xout[(size_t)row*CC + tid + 256] = o1;
    if (ohi) {
        float hm = hmask ? hmask[row] : 1.0f;
        __nv_bfloat16 hh, ll;
        split_bf16(o0 * hm, hh, ll);
        ohi[(size_t)row*CC + tid] = hh;  olo[(size_t)row*CC + tid] = ll;
        split_bf16(o1 * hm, hh, ll);
        ohi[(size_t)row*CC + tid + 256] = hh;  olo[(size_t)row*CC + tid + 256] = ll;
    }
}

// ---------------- host orchestration ---------------------------------------
extern "C" void kernel_launch(void* const* d_in, const int* in_sizes, int n_in,
                              void* d_out, int out_size)
{
    const float* x    = (const float*)d_in[0];
    const float* mask = (const float*)d_in[1];
    const float* Wq   = (const float*)d_in[2];
    const float* bq   = (const float*)d_in[3];
    const float* Wk   = (const float*)d_in[4];
    const float* bk   = (const float*)d_in[5];
    const float* Wv   = (const float*)d_in[6];
    const float* bv   = (const float*)d_in[7];
    const float* Wo   = (const float*)d_in[8];
    const float* bo   = (const float*)d_in[9];
    const float* erk  = (const float*)d_in[10];
    const float* erv  = (const float*)d_in[11];
    const float* ln1s = (const float*)d_in[12];
    const float* ln1b = (const float*)d_in[13];
    const float* W1   = (const float*)d_in[14];
    const float* b1   = (const float*)d_in[15];
    const float* W2   = (const float*)d_in[16];
    const float* b2   = (const float*)d_in[17];
    const float* ln2s = (const float*)d_in[18];
    const float* ln2b = (const float*)d_in[19];
    float* out = (float*)d_out;

    float *px, *py, *pbias;
    __nv_bfloat16 *xhi, *xlo, *qkvh, *qkvl, *paoh, *paol, *h1h, *h1l, *whi, *wlo;
    cudaGetSymbolAddress((void**)&px,   g_x);
    cudaGetSymbolAddress((void**)&py,   g_y);
    cudaGetSymbolAddress((void**)&pbias,g_bias);
    cudaGetSymbolAddress((void**)&xhi,  g_xhi);
    cudaGetSymbolAddress((void**)&xlo,  g_xlo);
    cudaGetSymbolAddress((void**)&qkvh, g_qkvhi);
    cudaGetSymbolAddress((void**)&qkvl, g_qkvlo);
    cudaGetSymbolAddress((void**)&paoh, g_paohi);
    cudaGetSymbolAddress((void**)&paol, g_paolo);
    cudaGetSymbolAddress((void**)&h1h,  g_h1hi);
    cudaGetSymbolAddress((void**)&h1l,  g_h1lo);
    cudaGetSymbolAddress((void**)&whi,  g_whi);
    cudaGetSymbolAddress((void**)&wlo,  g_wlo);

    cudaFuncSetAttribute(mma_gemm_kernel, cudaFuncAttributeMaxDynamicSharedMemorySize, DSMEM_G);
    cudaFuncSetAttribute(flash_kernel,    cudaFuncAttributeMaxDynamicSharedMemorySize, DSMEM_F);

    const int NE = BT * CC;
    init_kernel<<<(NE + 255)/256, 256>>>(x, mask, px, xhi, xlo);

    dim3 gQKV(QKVC/128, BT/128);   // 12 x 48
    dim3 gWoP(CC/128, BT/128);     // 4 x 48
    dim3 gFF1(FF/128, BT/128);     // 16 x 48
    dim3 gWc(CC/32, CC/32);
    dim3 gW1(FF/32, CC/32);
    dim3 gW2(CC/32, FF/32);
    dim3 blkW(32, 8);
    dim3 gFlash(TT/128, BB*HH);    // 6 x 64

    for (int l = 0; l < LL; l++) {
        const float* Wql = Wq + (size_t)l*CC*CC;
        const float* Wkl = Wk + (size_t)l*CC*CC;
        const float* Wvl = Wv + (size_t)l*CC*CC;
        const float* Wol = Wo + (size_t)l*CC*CC;  const float* bol = bo + (size_t)l*CC;
        const float* W1l = W1 + (size_t)l*CC*FF;  const float* b1l = b1 + (size_t)l*FF;
        const float* W2l = W2 + (size_t)l*FF*CC;  const float* b2l = b2 + (size_t)l*CC;
        const float* rkl = erk + (size_t)l*NWIN*KC;
        const float* rvl = erv + (size_t)l*NWIN*KC;

        // --- fused QKV projection (bf16 hi/lo out) ---
        packbias_kernel<<<(QKVC + 255)/256, 256>>>(bq + (size_t)l*CC, bk + (size_t)l*CC,
                                                   bv + (size_t)l*CC, pbias);
        convertWt_kernel<<<gWc, blkW>>>(Wql, whi,                   wlo,                   CC, CC);
        convertWt_kernel<<<gWc, blkW>>>(Wkl, whi + (size_t)CC*CC,   wlo + (size_t)CC*CC,   CC, CC);
        convertWt_kernel<<<gWc, blkW>>>(Wvl, whi + (size_t)2*CC*CC, wlo + (size_t)2*CC*CC, CC, CC);
        mma_gemm_kernel<<<gQKV, 256, DSMEM_G>>>(xhi, xlo, whi, wlo, pbias,
                                                nullptr, qkvh, qkvl, nullptr, BT, QKVC, CC, 0);

        // --- fused attention (scores + softmax + PV + both rel bands) ---
        flash_kernel<<<gFlash, 256, DSMEM_F>>>(qkvh, qkvl, rkl, rvl, mask, paoh, paol);

        // --- output projection + LN1 (hi/lo masked for FFN1) ---
        convertWt_kernel<<<gWc, blkW>>>(Wol, whi, wlo, CC, CC);
        mma_gemm_kernel<<<gWoP, 256, DSMEM_G>>>(paoh, paol, whi, wlo, bol,
                                                py, nullptr, nullptr, nullptr, BT, CC, CC, 0);
        addln_kernel<<<BT, 256>>>(px, py, nullptr, ln1s + (size_t)l*CC, ln1b + (size_t)l*CC,
                                  px, xhi, xlo, mask);

        // --- FFN ---
        convertWt_kernel<<<gW1, blkW>>>(W1l, whi, wlo, CC, FF);
        mma_gemm_kernel<<<gFF1, 256, DSMEM_G>>>(xhi, xlo, whi, wlo, b1l,
                                                nullptr, h1h, h1l, mask, BT, FF, CC, 1);
        convertWt_kernel<<<gW2, blkW>>>(W2l, whi, wlo, FF, CC);
        mma_gemm_kernel<<<gWoP, 256, DSMEM_G>>>(h1h, h1l, whi, wlo, b2l,
                                                py, nullptr, nullptr, nullptr, BT, CC, FF, 0);
        addln_kernel<<<BT, 256>>>(px, py, mask, ln2s + (size_t)l*CC, ln2b + (size_t)l*CC,
                                  px, xhi, xlo, nullptr);
    }

    maskmul_kernel<<<(NE + 255)/256, 256>>>(px, mask, out, NE);
}

// round 6
// speedup vs baseline: 2.9627x; 1.0910x over previous
#include <cuda_runtime.h>
#include <cuda_bf16.h>
#include <cstdint>
#include <cstddef>

#define BB   8
#define TT   768
#define CC   512
#define FF   2048
#define HH   8
#define KC   64
#define LL   6
#define BT   (BB*TT)      // 6144
#define QKVC (3*CC)       // 1536
#define NWIN 9

// prepacked weight layout (per layer, row-major [N,K] transposed):
//   rows 0..1535   : QKV  (q,k,v stacked)   N=QKVC K=CC
//   OFF_WO         : Wo^T                   N=CC   K=CC
//   OFF_W1         : W1^T                   N=FF   K=CC
//   OFF_W2         : W2^T                   N=CC   K=FF
#define OFF_WO  ((size_t)QKVC*CC)                 // 786432
#define OFF_W1  (OFF_WO + (size_t)CC*CC)          // 1048576
#define OFF_W2  (OFF_W1 + (size_t)FF*CC)          // 2097152
#define WSTRIDE (OFF_W2 + (size_t)CC*FF)          // 3145728

// ---------------- scratch (device globals: allocation-free) ----------------
__device__ float g_x [BT*CC];
__device__ float g_y [BT*CC];
__device__ float g_bias[LL*QKVC];
__device__ __nv_bfloat16 g_xhi [BT*CC];
__device__ __nv_bfloat16 g_xlo [BT*CC];
__device__ __nv_bfloat16 g_qkvhi[(size_t)BT*QKVC];
__device__ __nv_bfloat16 g_qkvlo[(size_t)BT*QKVC];
__device__ __nv_bfloat16 g_paohi[BT*CC];
__device__ __nv_bfloat16 g_paolo[BT*CC];
__device__ __nv_bfloat16 g_h1hi[(size_t)BT*FF];
__device__ __nv_bfloat16 g_h1lo[(size_t)BT*FF];
__device__ __nv_bfloat16 g_whi[(size_t)LL*WSTRIDE];
__device__ __nv_bfloat16 g_wlo[(size_t)LL*WSTRIDE];

// ======================= baseline-PTX helpers ===============================
static __device__ __forceinline__ uint32_t smem_u32(const void* p) {
    uint32_t a;
    asm("{ .reg .u64 t; cvta.to.shared.u64 t, %1; cvt.u32.u64 %0, t; }" : "=r"(a) : "l"(p));
    return a;
}
#define CP_ASYNC16(saddr, gptr) \
    asm volatile("cp.async.ca.shared.global [%0], [%1], 16;" :: "r"(saddr), "l"(gptr))
#define CP_COMMIT() asm volatile("cp.async.commit_group;")
#define CP_WAIT(n)  asm volatile("cp.async.wait_group %0;" :: "n"(n))

#define LDMX4(r0, r1, r2, r3, addr) \
    asm volatile("ldmatrix.sync.aligned.m8n8.x4.shared.b16 {%0,%1,%2,%3}, [%4];" \
                 : "=r"(r0), "=r"(r1), "=r"(r2), "=r"(r3) : "r"(addr))
#define LDMX4T(r0, r1, r2, r3, addr) \
    asm volatile("ldmatrix.sync.aligned.m8n8.x4.trans.shared.b16 {%0,%1,%2,%3}, [%4];" \
                 : "=r"(r0), "=r"(r1), "=r"(r2), "=r"(r3) : "r"(addr))

#define MMA16816(d, a, b) \
    asm volatile("mma.sync.aligned.m16n8k16.row.col.f32.bf16.bf16.f32 " \
                 "{%0,%1,%2,%3}, {%4,%5,%6,%7}, {%8,%9}, {%0,%1,%2,%3};" \
                 : "+f"((d)[0]), "+f"((d)[1]), "+f"((d)[2]), "+f"((d)[3]) \
                 : "r"((a)[0]), "r"((a)[1]), "r"((a)[2]), "r"((a)[3]), \
                   "r"((b)[0]), "r"((b)[1]))

static __device__ __forceinline__ void split_bf16(float v, __nv_bfloat16& h, __nv_bfloat16& l) {
    h = __float2bfloat16(v);
    l = __float2bfloat16(v - __bfloat162float(h));
}
static __device__ __forceinline__ uint32_t pack_hi2(float a, float b) {
    __nv_bfloat162 p = __halves2bfloat162(__float2bfloat16(a), __float2bfloat16(b));
    return *(uint32_t*)&p;
}
static __device__ __forceinline__ uint32_t pack_lo2(float a, float b) {
    __nv_bfloat16 ha = __float2bfloat16(a), hb = __float2bfloat16(b);
    __nv_bfloat162 p = __halves2bfloat162(__float2bfloat16(a - __bfloat162float(ha)),
                                          __float2bfloat16(b - __bfloat162float(hb)));
    return *(uint32_t*)&p;
}

// ======================= small utility kernels ==============================
__global__ void init_kernel(const float* __restrict__ X, const float* __restrict__ mask,
                            float* __restrict__ Xo,
                            __nv_bfloat16* __restrict__ hi, __nv_bfloat16* __restrict__ lo)
{
    int i = blockIdx.x * 256 + threadIdx.x;
    if (i >= BT*CC) return;
    float v = X[i] * mask[i / CC];
    Xo[i] = v;
    __nv_bfloat16 h, l; split_bf16(v, h, l);
    hi[i] = h; lo[i] = l;
}

__global__ void maskmul_kernel(const float* __restrict__ in, const float* __restrict__ mask,
                               float* __restrict__ out, int n)
{
    int i = blockIdx.x * 256 + threadIdx.x;
    if (i < n) out[i] = in[i] * mask[i / CC];
}

__global__ void packbias_kernel(const float* __restrict__ bq, const float* __restrict__ bk,
                                const float* __restrict__ bv, float* __restrict__ dst)
{
    int i = blockIdx.x * 256 + threadIdx.x;
    if (i >= LL*QKVC) return;
    int l = i / QKVC, c = i % QKVC;
    dst[i] = (c < CC) ? bq[l*CC + c] : (c < 2*CC) ? bk[l*CC + c - CC] : bv[l*CC + c - 2*CC];
}

// batched: W [LL, K, N] fp32 -> dst [LL(dstStride), N, K] bf16 hi/lo
__global__ void convertWt_batch(const float* __restrict__ W, size_t srcStride,
                                __nv_bfloat16* __restrict__ hi, __nv_bfloat16* __restrict__ lo,
                                size_t dstOff, int K, int N)
{
    __shared__ float t[32][33];
    int l = blockIdx.z;
    const float* src = W + (size_t)l * srcStride;
    __nv_bfloat16* dh = hi + (size_t)l * WSTRIDE + dstOff;
    __nv_bfloat16* dl = lo + (size_t)l * WSTRIDE + dstOff;
    int n0 = blockIdx.x * 32, k0 = blockIdx.y * 32;
    int tx = threadIdx.x, ty = threadIdx.y;   // 32 x 8
    #pragma unroll
    for (int r = 0; r < 32; r += 8)
        t[ty + r][tx] = src[(size_t)(k0 + ty + r) * N + n0 + tx];
    __syncthreads();
    #pragma unroll
    for (int r = 0; r < 32; r += 8) {
        float v = t[tx][ty + r];
        __nv_bfloat16 h, l2; split_bf16(v, h, l2);
        size_t o = (size_t)(n0 + ty + r) * K + k0 + tx;
        dh[o] = h; dl[o] = l2;
    }
}

// ======================= dense tensor-core GEMM =============================
// Tile 128x64, BK=32, 256 thr (warps 4Mx2N, warp tile 32x32), 2 CTAs/SM.
#define ATILE_B (128*80)
#define BTILE_B (64*80)
#define STAGEB  (2*ATILE_B + 2*BTILE_B)   // 30720
#define DSMEM_G (2*STAGEB)                // 61440

__global__ void __launch_bounds__(256, 2)
mma_gemm_kernel(const __nv_bfloat16* __restrict__ aHi, const __nv_bfloat16* __restrict__ aLo,
                const __nv_bfloat16* __restrict__ bHi, const __nv_bfloat16* __restrict__ bLo,
                const float* __restrict__ bias, float* __restrict__ C,
                __nv_bfloat16* __restrict__ Chi, __nv_bfloat16* __restrict__ Clo,
                const float* __restrict__ rowmask,
                int M, int N, int K, int relu)
{
    extern __shared__ unsigned char dsm[];
    const int tid  = threadIdx.x;
    const int lane = tid & 31, warp = tid >> 5;
    const int wm = warp >> 1, wn = warp & 1;        // 4 x 2 warp grid
    const int bm = blockIdx.y * 128;
    const int bn = blockIdx.x * 64;
    const uint32_t sbase = smem_u32(dsm);

    float acc[2][4][4];
    #pragma unroll
    for (int i = 0; i < 2; i++)
        #pragma unroll
        for (int j = 0; j < 4; j++)
            #pragma unroll
            for (int e = 0; e < 4; e++) acc[i][j][e] = 0.f;

    const int nk = K >> 5;

    auto load_stage = [&](int kt, int s) {
        const int kt0 = kt << 5;
        uint32_t sst = sbase + s * STAGEB;
        // A hi/lo: 128x32
        #pragma unroll
        for (int t = 0; t < 2; t++) {
            const __nv_bfloat16* src = t ? aLo : aHi;
            uint32_t stile = sst + t * ATILE_B;
            #pragma unroll
            for (int u = 0; u < 2; u++) {
                int c = u * 256 + tid;
                int row = c >> 2, col = (c & 3) * 8;
                CP_ASYNC16(stile + row * 80 + col * 2,
                           src + (size_t)(bm + row) * K + kt0 + col);
            }
        }
        // B hi/lo: 64x32
        #pragma unroll
        for (int t = 0; t < 2; t++) {
            const __nv_bfloat16* src = t ? bLo : bHi;
            uint32_t stile = sst + 2 * ATILE_B + t * BTILE_B;
            int row = tid >> 2, col = (tid & 3) * 8;
            CP_ASYNC16(stile + row * 80 + col * 2,
                       src + (size_t)(bn + row) * K + kt0 + col);
        }
    };

    load_stage(0, 0);
    CP_COMMIT();

    int buf = 0;
    for (int kt = 0; kt < nk; kt++) {
        if (kt + 1 < nk) { load_stage(kt + 1, buf ^ 1); CP_COMMIT(); CP_WAIT(1); }
        else             { CP_WAIT(0); }
        __syncthreads();

        uint32_t sAh = sbase + buf * STAGEB;
        uint32_t sAl = sAh + ATILE_B;
        uint32_t sBh = sAh + 2 * ATILE_B;
        uint32_t sBl = sBh + BTILE_B;

        #pragma unroll
        for (int ks = 0; ks < 32; ks += 16) {
            uint32_t Ah[2][4], Al[2][4], Bh[4][2], Bl[4][2];
            #pragma unroll
            for (int i = 0; i < 2; i++) {
                uint32_t off = (uint32_t)((wm * 32 + i * 16 + (lane & 15)) * 80
                                          + ((lane >> 4) * 8 + ks) * 2);
                LDMX4(Ah[i][0], Ah[i][1], Ah[i][2], Ah[i][3], sAh + off);
                LDMX4(Al[i][0], Al[i][1], Al[i][2], Al[i][3], sAl + off);
            }
            #pragma unroll
            for (int p = 0; p < 2; p++) {
                int sub = lane >> 3;
                uint32_t off = (uint32_t)((wn * 32 + p * 16 + (lane & 7) + (sub >> 1) * 8) * 80
                                          + ((sub & 1) * 8 + ks) * 2);
                LDMX4(Bh[2*p][0], Bh[2*p][1], Bh[2*p+1][0], Bh[2*p+1][1], sBh + off);
                LDMX4(Bl[2*p][0], Bl[2*p][1], Bl[2*p+1][0], Bl[2*p+1][1], sBl + off);
            }
            #pragma unroll
            for (int i = 0; i < 2; i++)
                #pragma unroll
                for (int j = 0; j < 4; j++)
                    MMA16816(acc[i][j], Ah[i], Bh[j]);
            #pragma unroll
            for (int i = 0; i < 2; i++)
                #pragma unroll
                for (int j = 0; j < 4; j++)
                    MMA16816(acc[i][j], Al[i], Bh[j]);
            #pragma unroll
            for (int i = 0; i < 2; i++)
                #pragma unroll
                for (int j = 0; j < 4; j++)
                    MMA16816(acc[i][j], Ah[i], Bl[j]);
        }
        __syncthreads();
        buf ^= 1;
    }

    #pragma unroll
    for (int i = 0; i < 2; i++) {
        int r = bm + wm * 32 + i * 16 + (lane >> 2);
        float m0 = rowmask ? rowmask[r]     : 1.f;
        float m1 = rowmask ? rowmask[r + 8] : 1.f;
        #pragma unroll
        for (int j = 0; j < 4; j++) {
            int cix = bn + wn * 32 + j * 8 + (lane & 3) * 2;
            float b0 = bias[cix], b1 = bias[cix + 1];
            float v[4];
            v[0] = acc[i][j][0] + b0; v[1] = acc[i][j][1] + b1;
            v[2] = acc[i][j][2] + b0; v[3] = acc[i][j][3] + b1;
            if (relu) {
                #pragma unroll
                for (int e = 0; e < 4; e++) v[e] = fmaxf(v[e], 0.f);
            }
            v[0] *= m0; v[1] *= m0; v[2] *= m1; v[3] *= m1;
            if (C) {
                *(float2*)(C + (size_t)r * N + cix)       = make_float2(v[0], v[1]);
                *(float2*)(C + (size_t)(r + 8) * N + cix) = make_float2(v[2], v[3]);
            }
            if (Chi) {
                *(uint32_t*)(Chi + (size_t)r * N + cix)       = pack_hi2(v[0], v[1]);
                *(uint32_t*)(Clo + (size_t)r * N + cix)       = pack_lo2(v[0], v[1]);
                *(uint32_t*)(Chi + (size_t)(r + 8) * N + cix) = pack_hi2(v[2], v[3]);
                *(uint32_t*)(Clo + (size_t)(r + 8) * N + cix) = pack_lo2(v[2], v[3]);
            }
        }
    }
}

// ======================= fused flash attention ==============================
#define FLDT 72
#define FT_B (128*FLDT*2)     // 18432 B
#define DSMEM_F (10*FT_B + 6144 + 6144 + 2304 + 3072)

__global__ void __launch_bounds__(256, 1)
flash_kernel(const __nv_bfloat16* __restrict__ qkvh, const __nv_bfloat16* __restrict__ qkvl,
             const float* __restrict__ rk, const float* __restrict__ rv,
             const float* __restrict__ mask,
             __nv_bfloat16* __restrict__ ohi, __nv_bfloat16* __restrict__ olo)
{
    extern __shared__ unsigned char dsm[];
    const int tid  = threadIdx.x;
    const int lane = tid & 31, warp = tid >> 5;
    const int gq = lane >> 2, qt = lane & 3;
    const int bh = blockIdx.y, b = bh >> 3, h = bh & 7;
    const int i0 = blockIdx.x * 128;
    const uint32_t sbase = smem_u32(dsm);
    const uint32_t sQh = sbase, sQl = sbase + FT_B;

    float* band  = (float*)(dsm + 10*FT_B);
    float* rel9  = band + 128*12;
    float* rvs   = rel9 + 128*12;
    float* maskS = rvs + 9*64;

    #pragma unroll
    for (int t = 0; t < 2; t++) {
        const __nv_bfloat16* src = t ? qkvl : qkvh;
        uint32_t tile = sQh + t * FT_B;
        #pragma unroll
        for (int u = 0; u < 4; u++) {
            int c = u * 256 + tid;
            int row = c >> 3, col = (c & 7) * 8;
            const __nv_bfloat16* g = src + (size_t)(b*TT + i0 + row) * QKVC + h*KC + col;
            CP_ASYNC16(tile + (row * FLDT + col) * 2, g);
        }
    }
    CP_COMMIT();

    auto load_kv = [&](int jt, int s) {
        int j0 = jt * 128;
        uint32_t sst = sbase + 2*FT_B + s * 4*FT_B;
        #pragma unroll
        for (int t = 0; t < 4; t++) {
            const __nv_bfloat16* src = (t & 1) ? qkvl : qkvh;
            const int coff = (t < 2) ? CC + h*KC : 2*CC + h*KC;
            uint32_t tile = sst + t * FT_B;
            #pragma unroll
            for (int u = 0; u < 4; u++) {
                int c = u * 256 + tid;
                int row = c >> 3, col = (c & 7) * 8;
                const __nv_bfloat16* g = src + (size_t)(b*TT + j0 + row) * QKVC + coff + col;
                CP_ASYNC16(tile + (row * FLDT + col) * 2, g);
            }
        }
    };
    load_kv(0, 0);
    CP_COMMIT();

    for (int idx = tid; idx < TT; idx += 256) maskS[idx] = mask[b*TT + idx];
    for (int idx = tid; idx < NWIN*KC; idx += 256) rvs[idx] = rv[idx];
    for (int idx = tid; idx < 128*NWIN; idx += 256)
        band[(idx/NWIN)*12 + (idx%NWIN)] = -1e30f;

    CP_WAIT(1);
    __syncthreads();

    for (int idx = tid; idx < 128*NWIN; idx += 256) {
        int r = idx / NWIN, j5 = idx % NWIN;
        const float* rkj = rk + j5 * KC;
        float s = 0.f;
        #pragma unroll 8
        for (int d = 0; d < KC; d++) {
            float qv = __bfloat162float(*(__nv_bfloat16*)(dsm + (r*FLDT + d)*2))
                     + __bfloat162float(*(__nv_bfloat16*)(dsm + FT_B + (r*FLDT + d)*2));
            s += qv * rkj[d];
        }
        rel9[r*12 + j5] = s * 0.125f;
    }
    __syncthreads();

    const int lr0 = warp*16 + gq, lr1 = lr0 + 8;
    const float mq0 = maskS[i0 + lr0], mq1 = maskS[i0 + lr1];

    float m0 = -1e30f, m1 = -1e30f, l0 = 0.f, l1 = 0.f;
    float O[8][4];
    #pragma unroll
    for (int nb = 0; nb < 8; nb++)
        #pragma unroll
        for (int e = 0; e < 4; e++) O[nb][e] = 0.f;

    for (int jt = 0; jt < 6; jt++) {
        if (jt + 1 < 6) { load_kv(jt + 1, (jt + 1) & 1); CP_COMMIT(); CP_WAIT(1); }
        else            { CP_WAIT(0); }
        __syncthreads();

        uint32_t sst = sbase + 2*FT_B + (jt & 1) * 4*FT_B;
        uint32_t sKh = sst, sKl = sst + FT_B, sVh = sst + 2*FT_B, sVl = sst + 3*FT_B;
        const int j0 = jt * 128;

        float sacc[16][4];
        #pragma unroll
        for (int nb = 0; nb < 16; nb++)
            #pragma unroll
            for (int e = 0; e < 4; e++) sacc[nb][e] = 0.f;

        #pragma unroll
        for (int ks = 0; ks < 64; ks += 16) {
            uint32_t Ah[4], Al[4];
            uint32_t aoff = (uint32_t)(((warp*16 + (lane & 15)) * FLDT + (lane >> 4) * 8 + ks) * 2);
            LDMX4(Ah[0], Ah[1], Ah[2], Ah[3], sQh + aoff);
            LDMX4(Al[0], Al[1], Al[2], Al[3], sQl + aoff);
            #pragma unroll
            for (int p = 0; p < 8; p++) {
                int sub = lane >> 3;
                uint32_t boff = (uint32_t)(((p*16 + (lane & 7) + (sub >> 1) * 8) * FLDT
                                            + (sub & 1) * 8 + ks) * 2);
                uint32_t Bh[2][2], Bl[2][2];
                LDMX4(Bh[0][0], Bh[0][1], Bh[1][0], Bh[1][1], sKh + boff);
                LDMX4(Bl[0][0], Bl[0][1], Bl[1][0], Bl[1][1], sKl + boff);
                MMA16816(sacc[2*p],   Ah, Bh[0]); MMA16816(sacc[2*p+1], Ah, Bh[1]);
                MMA16816(sacc[2*p],   Al, Bh[0]); MMA16816(sacc[2*p+1], Al, Bh[1]);
                MMA16816(sacc[2*p],   Ah, Bl[0]); MMA16816(sacc[2*p+1], Ah, Bl[1]);
            }
        }

        #pragma unroll
        for (int nb = 0; nb < 16; nb++) {
            int colb = j0 + nb*8 + qt*2;
            #pragma unroll
            for (int e = 0; e < 4; e++) {
                int row = (e < 2) ? (i0 + lr0) : (i0 + lr1);
                int lr  = (e < 2) ? lr0 : lr1;
                float mq = (e < 2) ? mq0 : mq1;
                int col = colb + (e & 1);
                float v = sacc[nb][e] * 0.125f;
                int d = col - row + 4;
                if ((unsigned)d < (unsigned)NWIN) v += rel9[lr*12 + d];
                if (mq * maskS[col] == 0.f) v = -10000.f;
                if ((unsigned)d < (unsigned)NWIN) band[lr*12 + d] = v;
                sacc[nb][e] = v;
            }
        }

        float mx0 = -1e30f, mx1 = -1e30f;
        #pragma unroll
        for (int nb = 0; nb < 16; nb++) {
            mx0 = fmaxf(mx0, fmaxf(sacc[nb][0], sacc[nb][1]));
            mx1 = fmaxf(mx1, fmaxf(sacc[nb][2], sacc[nb][3]));
        }
        mx0 = fmaxf(mx0, __shfl_xor_sync(0xffffffffu, mx0, 1));
        mx0 = fmaxf(mx0, __shfl_xor_sync(0xffffffffu, mx0, 2));
        mx1 = fmaxf(mx1, __shfl_xor_sync(0xffffffffu, mx1, 1));
        mx1 = fmaxf(mx1, __shfl_xor_sync(0xffffffffu, mx1, 2));
        float mn0 = fmaxf(m0, mx0), mn1 = fmaxf(m1, mx1);
        float f0 = __expf(m0 - mn0), f1 = __expf(m1 - mn1);
        float s0 = 0.f, s1 = 0.f;
        #pragma unroll
        for (int nb = 0; nb < 16; nb++) {
            sacc[nb][0] = __expf(sacc[nb][0] - mn0);
            sacc[nb][1] = __expf(sacc[nb][1] - mn0);
            sacc[nb][2] = __expf(sacc[nb][2] - mn1);
            sacc[nb][3] = __expf(sacc[nb][3] - mn1);
            s0 += sacc[nb][0] + sacc[nb][1];
            s1 += sacc[nb][2] + sacc[nb][3];
        }
        s0 += __shfl_xor_sync(0xffffffffu, s0, 1);
        s0 += __shfl_xor_sync(0xffffffffu, s0, 2);
        s1 += __shfl_xor_sync(0xffffffffu, s1, 1);
        s1 += __shfl_xor_sync(0xffffffffu, s1, 2);
        l0 = l0 * f0 + s0;  l1 = l1 * f1 + s1;
        m0 = mn0;  m1 = mn1;
        #pragma unroll
        for (int nb = 0; nb < 8; nb++) {
            O[nb][0] *= f0; O[nb][1] *= f0; O[nb][2] *= f1; O[nb][3] *= f1;
        }

        #pragma unroll
        for (int kb = 0; kb < 8; kb++) {
            uint32_t Ph[4], Pl[4];
            Ph[0] = pack_hi2(sacc[2*kb][0],   sacc[2*kb][1]);
            Ph[1] = pack_hi2(sacc[2*kb][2],   sacc[2*kb][3]);
            Ph[2] = pack_hi2(sacc[2*kb+1][0], sacc[2*kb+1][1]);
            Ph[3] = pack_hi2(sacc[2*kb+1][2], sacc[2*kb+1][3]);
            Pl[0] = pack_lo2(sacc[2*kb][0],   sacc[2*kb][1]);
            Pl[1] = pack_lo2(sacc[2*kb][2],   sacc[2*kb][3]);
            Pl[2] = pack_lo2(sacc[2*kb+1][0], sacc[2*kb+1][1]);
            Pl[3] = pack_lo2(sacc[2*kb+1][2], sacc[2*kb+1][3]);
            #pragma unroll
            for (int vb = 0; vb < 4; vb++) {
                int g = lane >> 3;
                int krow = kb*16 + (g & 1) * 8 + (lane & 7);
                int ncol = vb*16 + (g >> 1) * 8;
                uint32_t off = (uint32_t)((krow * FLDT + ncol) * 2);
                uint32_t Vh[2][2], Vl[2][2];
                LDMX4T(Vh[0][0], Vh[0][1], Vh[1][0], Vh[1][1], sVh + off);
                LDMX4T(Vl[0][0], Vl[0][1], Vl[1][0], Vl[1][1], sVl + off);
                MMA16816(O[2*vb],   Ph, Vh[0]); MMA16816(O[2*vb+1], Ph, Vh[1]);
                MMA16816(O[2*vb],   Pl, Vh[0]); MMA16816(O[2*vb+1], Pl, Vh[1]);
                MMA16816(O[2*vb],   Ph, Vl[0]); MMA16816(O[2*vb+1], Ph, Vl[1]);
            }
        }
        __syncthreads();
    }

    float inv0 = 1.f / l0, inv1 = 1.f / l1;
    float bp0[NWIN], bp1[NWIN];
    #pragma unroll
    for (int j5 = 0; j5 < NWIN; j5++) {
        bp0[j5] = __expf(band[lr0*12 + j5] - m0) * inv0;
        bp1[j5] = __expf(band[lr1*12 + j5] - m1) * inv1;
    }
    #pragma unroll
    for (int nb = 0; nb < 8; nb++) {
        int c = nb*8 + qt*2;
        float v0 = O[nb][0] * inv0, v1 = O[nb][1] * inv0;
        float v2 = O[nb][2] * inv1, v3 = O[nb][3] * inv1;
        #pragma unroll
        for (int j5 = 0; j5 < NWIN; j5++) {
            float r0 = rvs[j5*KC + c], r1 = rvs[j5*KC + c + 1];
            v0 += bp0[j5]*r0; v1 += bp0[j5]*r1;
            v2 += bp1[j5]*r0; v3 += bp1[j5]*r1;
        }
        size_t o0 = (size_t)(b*TT + i0 + lr0) * CC + h*KC + c;
        size_t o1 = (size_t)(b*TT + i0 + lr1) * CC + h*KC + c;
        *(uint32_t*)(ohi + o0) = pack_hi2(v0, v1);
        *(uint32_t*)(olo + o0) = pack_lo2(v0, v1);
        *(uint32_t*)(ohi + o1) = pack_hi2(v2, v3);
        *(uint32_t*)(olo + o1) = pack_lo2(v2, v3);
    }
}

// ---------------- fused residual + LayerNorm (+ bf16 hi/lo out) ------------
__global__ void __launch_bounds__(256)
addln_kernel(const float* __restrict__ X, const float* __restrict__ Y,
             const float* __restrict__ ymask, const float* __restrict__ sc,
             const float* __restrict__ bi, float* __restrict__ Xout,
             __nv_bfloat16* __restrict__ ohi, __nv_bfloat16* __restrict__ olo,
             const float* __restrict__ hmask)
{
    int row = blockIdx.x;
    int tid = threadIdx.x;
    float m = ymask ? ymask[row] : 1.0f;
    const float* xr = X + (size_t)row * CC;
    const float* yr = Y + (size_t)row * CC;
    float v0 = xr[tid]       + yr[tid]       * m;
    float v1 = xr[tid + 256] + yr[tid + 256] * m;

    __shared__ float red[256];
    red[tid] = v0 + v1; __syncthreads();
    for (int s = 128; s > 0; s >>= 1) {
        if (tid < s) red[tid] += red[tid+s];
        __syncthreads();
    }
    float mean = red[0] * (1.0f / CC);
    __syncthreads();
    float d0 = v0 - mean, d1 = v1 - mean;
    red[tid] = d0*d0 + d1*d1; __syncthreads();
    for (int s = 128; s > 0; s >>= 1) {
        if (tid < s) red[tid] += red[tid+s];
        __syncthreads();
    }
    float r = rsqrtf(red[0] * (1.0f / CC) + 1e-6f);
    float o0 = d0 * r * sc[tid]       + bi[tid];
    float o1 = d1 * r * sc[tid + 256] + bi[tid + 256];
    Xout[(size_t)row*CC + tid]       = o0;
    Xout[(size_t)row*CC + tid + 256] = o1;
    if (ohi) {
        float hm = hmask ? hmask[row] : 1.0f;
        __nv_bfloat16 hh, ll;
        split_bf16(o0 * hm, hh, ll);
        ohi[(size_t)row*CC + tid] = hh;  olo[(size_t)row*CC + tid] = ll;
        split_bf16(o1 * hm, hh, ll);
        ohi[(size_t)row*CC + tid + 256] = hh;  olo[(size_t)row*CC + tid + 256] = ll;
    }
}

// ---------------- host orchestration ---------------------------------------
extern "C" void kernel_launch(void* const* d_in, const int* in_sizes, int n_in,
                              void* d_out, int out_size)
{
    const float* x    = (const float*)d_in[0];
    const float* mask = (const float*)d_in[1];
    const float* Wq   = (const float*)d_in[2];
    const float* bq   = (const float*)d_in[3];
    const float* Wk   = (const float*)d_in[4];
    const float* bk   = (const float*)d_in[5];
    const float* Wv   = (const float*)d_in[6];
    const float* bv   = (const float*)d_in[7];
    const float* Wo   = (const float*)d_in[8];
    const float* bo   = (const float*)d_in[9];
    const float* erk  = (const float*)d_in[10];
    const float* erv  = (const float*)d_in[11];
    const float* ln1s = (const float*)d_in[12];
    const float* ln1b = (const float*)d_in[13];
    const float* W1   = (const float*)d_in[14];
    const float* b1   = (const float*)d_in[15];
    const float* W2   = (const float*)d_in[16];
    const float* b2   = (const float*)d_in[17];
    const float* ln2s = (const float*)d_in[18];
    const float* ln2b = (const float*)d_in[19];
    float* out = (float*)d_out;

    float *px, *py, *pbias;
    __nv_bfloat16 *xhi, *xlo, *qkvh, *qkvl, *paoh, *paol, *h1h, *h1l, *whi, *wlo;
    cudaGetSymbolAddress((void**)&px,   g_x);
    cudaGetSymbolAddress((void**)&py,   g_y);
    cudaGetSymbolAddress((void**)&pbias,g_bias);
    cudaGetSymbolAddress((void**)&xhi,  g_xhi);
    cudaGetSymbolAddress((void**)&xlo,  g_xlo);
    cudaGetSymbolAddress((void**)&qkvh, g_qkvhi);
    cudaGetSymbolAddress((void**)&qkvl, g_qkvlo);
    cudaGetSymbolAddress((void**)&paoh, g_paohi);
    cudaGetSymbolAddress((void**)&paol, g_paolo);
    cudaGetSymbolAddress((void**)&h1h,  g_h1hi);
    cudaGetSymbolAddress((void**)&h1l,  g_h1lo);
    cudaGetSymbolAddress((void**)&whi,  g_whi);
    cudaGetSymbolAddress((void**)&wlo,  g_wlo);

    cudaFuncSetAttribute(mma_gemm_kernel, cudaFuncAttributeMaxDynamicSharedMemorySize, DSMEM_G);
    cudaFuncSetAttribute(flash_kernel,    cudaFuncAttributeMaxDynamicSharedMemorySize, DSMEM_F);

    const int NE = BT * CC;
    init_kernel<<<(NE + 255)/256, 256>>>(x, mask, px, xhi, xlo);

    // ---- batched weight prep (once per call, all layers) ----
    dim3 blkW(32, 8);
    convertWt_batch<<<dim3(CC/32, CC/32, LL), blkW>>>(Wq, (size_t)CC*CC, whi, wlo, 0,              CC, CC);
    convertWt_batch<<<dim3(CC/32, CC/32, LL), blkW>>>(Wk, (size_t)CC*CC, whi, wlo, (size_t)CC*CC,  CC, CC);
    convertWt_batch<<<dim3(CC/32, CC/32, LL), blkW>>>(Wv, (size_t)CC*CC, whi, wlo, (size_t)2*CC*CC,CC, CC);
    convertWt_batch<<<dim3(CC/32, CC/32, LL), blkW>>>(Wo, (size_t)CC*CC, whi, wlo, OFF_WO,         CC, CC);
    convertWt_batch<<<dim3(FF/32, CC/32, LL), blkW>>>(W1, (size_t)CC*FF, whi, wlo, OFF_W1,         CC, FF);
    convertWt_batch<<<dim3(CC/32, FF/32, LL), blkW>>>(W2, (size_t)FF*CC, whi, wlo, OFF_W2,         FF, CC);
    packbias_kernel<<<(LL*QKVC + 255)/256, 256>>>(bq, bk, bv, pbias);

    dim3 gQKV(QKVC/64, BT/128);   // 24 x 48
    dim3 gWoP(CC/64,  BT/128);    // 8 x 48
    dim3 gFF1(FF/64,  BT/128);    // 32 x 48
    dim3 gFlash(TT/128, BB*HH);   // 6 x 64

    for (int l = 0; l < LL; l++) {
        const __nv_bfloat16* wbh = whi + (size_t)l * WSTRIDE;
        const __nv_bfloat16* wbl = wlo + (size_t)l * WSTRIDE;
        const float* bol = bo + (size_t)l*CC;
        const float* b1l = b1 + (size_t)l*FF;
        const float* b2l = b2 + (size_t)l*CC;
        const float* rkl = erk + (size_t)l*NWIN*KC;
        const float* rvl = erv + (size_t)l*NWIN*KC;

        mma_gemm_kernel<<<gQKV, 256, DSMEM_G>>>(xhi, xlo, wbh, wbl, pbias + l*QKVC,
                                                nullptr, qkvh, qkvl, nullptr, BT, QKVC, CC, 0);

        flash_kernel<<<gFlash, 256, DSMEM_F>>>(qkvh, qkvl, rkl, rvl, mask, paoh, paol);

        mma_gemm_kernel<<<gWoP, 256, DSMEM_G>>>(paoh, paol, wbh + OFF_WO, wbl + OFF_WO, bol,
                                                py, nullptr, nullptr, nullptr, BT, CC, CC, 0);
        addln_kernel<<<BT, 256>>>(px, py, nullptr, ln1s + (size_t)l*CC, ln1b + (size_t)l*CC,
                                  px, xhi, xlo, mask);

        mma_gemm_kernel<<<gFF1, 256, DSMEM_G>>>(xhi, xlo, wbh + OFF_W1, wbl + OFF_W1, b1l,
                                                nullptr, h1h, h1l, mask, BT, FF, CC, 1);
        mma_gemm_kernel<<<gWoP, 256, DSMEM_G>>>(h1h, h1l, wbh + OFF_W2, wbl + OFF_W2, b2l,
                                                py, nullptr, nullptr, nullptr, BT, CC, FF, 0);
        addln_kernel<<<BT, 256>>>(px, py, mask, ln2s + (size_t)l*CC, ln2b + (size_t)l*CC,
                                  px, xhi, xlo, nullptr);
    }

    maskmul_kernel<<<(NE + 255)/256, 256>>>(px, mask, out, NE);
}